// round 5
// baseline (speedup 1.0000x reference)
#include <cuda_runtime.h>
#include <math.h>

#define NB 64
#define NT 512
#define NF 512
#define NDIN 1024
#define NH 1024
#define NZ 4096
#define NDOUT 128
#define SH (NB*NH)     // 65536 state elements per buffer
#define NBLK 128       // persistent blocks (1/SM, all co-resident)
#define KC 32          // K-chunk for k_rnn

typedef unsigned long long ull;

// Scratch (device globals; no dynamic allocation allowed)
__device__ float g_xin[(size_t)NT * NB * NDIN];   // tanh(x@Wi+bi), rows r = t*NB+b
__device__ float g_P0[(size_t)NT * NB * NZ];      // xin@W0 + b0
__device__ float g_h0[2 * SH];                    // double-buffered hidden states
__device__ float g_h1[2 * SH];

// grid barrier state
__device__ unsigned g_count;
__device__ volatile unsigned g_gen;

// ---------------------------------------------------------------------------
// packed f32x2 helpers (sm_103a dual-fp32 pipe, PTX-only)
// ---------------------------------------------------------------------------
__device__ __forceinline__ ull ffma2_(ull a, ull b, ull c) {
    ull d;
    asm("fma.rn.f32x2 %0, %1, %2, %3;" : "=l"(d) : "l"(a), "l"(b), "l"(c));
    return d;
}
__device__ __forceinline__ float2 unpack2_(ull v) {
    float2 r;
    asm("mov.b64 {%0, %1}, %2;" : "=f"(r.x), "=f"(r.y) : "l"(v));
    return r;
}

// ---------------------------------------------------------------------------
__global__ void k_init() {
    int idx = blockIdx.x * blockDim.x + threadIdx.x;
    if (idx < 2 * SH) { g_h0[idx] = 0.f; g_h1[idx] = 0.f; }
    if (idx == 0) { g_count = 0; g_gen = 0; }
}

// ---------------------------------------------------------------------------
// k_xin: xin[r, n] = tanh( x[b,t,:] @ Wi[:,n] + bi[n] ),  r = t*NB + b
// GEMM M=32768, K=512, N=1024. Tile 64x64, 256 threads, 4x4 per thread.
// ---------------------------------------------------------------------------
__global__ __launch_bounds__(256) void k_xin(const float* __restrict__ x,
                                             const float* __restrict__ Wi,
                                             const float* __restrict__ bi) {
    __shared__ float As[16][64];
    __shared__ float Bs[16][64];
    int tid = threadIdx.x;
    int tx = tid & 15, ty = tid >> 4;
    int n0 = blockIdx.x * 64;
    int row0 = blockIdx.y * 64;

    float acc[4][4] = {};

    int ar = tid & 63, akq = tid >> 6;
    int R = row0 + ar;
    int bb = R & 63, tt = R >> 6;               // r = t*NB + b
    const float* aptr = x + ((size_t)bb * NT + tt) * NF + akq * 4;
    int bkk = tid >> 4, bnq = tid & 15;
    const float* bptr = Wi + (size_t)bkk * NDIN + n0 + bnq * 4;

    float4 pa = *(const float4*)aptr;
    float4 pb = *(const float4*)bptr;

    const int NC = NF / 16;
    for (int c = 0; c < NC; c++) {
        As[akq * 4 + 0][ar] = pa.x; As[akq * 4 + 1][ar] = pa.y;
        As[akq * 4 + 2][ar] = pa.z; As[akq * 4 + 3][ar] = pa.w;
        *(float4*)&Bs[bkk][bnq * 4] = pb;
        __syncthreads();
        if (c + 1 < NC) {
            pa = *(const float4*)(aptr + (c + 1) * 16);
            pb = *(const float4*)(bptr + (size_t)(c + 1) * 16 * NDIN);
        }
#pragma unroll
        for (int kk = 0; kk < 16; kk++) {
            float4 a = *(const float4*)&As[kk][ty * 4];
            float4 b = *(const float4*)&Bs[kk][tx * 4];
            acc[0][0] += a.x * b.x; acc[0][1] += a.x * b.y; acc[0][2] += a.x * b.z; acc[0][3] += a.x * b.w;
            acc[1][0] += a.y * b.x; acc[1][1] += a.y * b.y; acc[1][2] += a.y * b.z; acc[1][3] += a.y * b.w;
            acc[2][0] += a.z * b.x; acc[2][1] += a.z * b.y; acc[2][2] += a.z * b.z; acc[2][3] += a.z * b.w;
            acc[3][0] += a.w * b.x; acc[3][1] += a.w * b.y; acc[3][2] += a.w * b.z; acc[3][3] += a.w * b.w;
        }
        __syncthreads();
    }
#pragma unroll
    for (int i = 0; i < 4; i++) {
        int r = row0 + ty * 4 + i;
#pragma unroll
        for (int jx = 0; jx < 4; jx++) {
            int n = n0 + tx * 4 + jx;
            g_xin[(size_t)r * NDIN + n] = tanhf(acc[i][jx] + bi[n]);
        }
    }
}

// ---------------------------------------------------------------------------
// k_p0: P0 = xin @ W0 + b0.  GEMM M=32768, K=1024, N=4096.
// Tile 128x64, 256 threads, 8x4 per thread, FFMA2 inner (rows packed,
// B duplicated in smem).
// ---------------------------------------------------------------------------
__global__ __launch_bounds__(256) void k_p0(const float* __restrict__ W0,
                                            const float* __restrict__ b0) {
    __shared__ float As[16][128];
    __shared__ float Bs2[16][128];   // duplicated: col c at [c*2], {v,v}
    int tid = threadIdx.x;
    int tx = tid & 15, ty = tid >> 4;
    int n0 = blockIdx.x * 64;
    int row0 = blockIdx.y * 128;

    ull acc2[4][4] = {};             // [rowpair][col]

    int ar = tid & 127, akq0 = tid >> 7;
    const float* aptr0 = g_xin + (size_t)(row0 + ar) * NDIN + akq0 * 4;
    const float* aptr1 = g_xin + (size_t)(row0 + ar) * NDIN + (akq0 + 2) * 4;
    int bkk = tid >> 4, bnq = tid & 15;
    const float* bptr = W0 + (size_t)bkk * NZ + n0 + bnq * 4;

    float4 pa0 = *(const float4*)aptr0;
    float4 pa1 = *(const float4*)aptr1;
    float4 pb  = *(const float4*)bptr;

    const int NC = NDIN / 16;
    for (int c = 0; c < NC; c++) {
        As[akq0 * 4 + 0][ar] = pa0.x; As[akq0 * 4 + 1][ar] = pa0.y;
        As[akq0 * 4 + 2][ar] = pa0.z; As[akq0 * 4 + 3][ar] = pa0.w;
        As[(akq0 + 2) * 4 + 0][ar] = pa1.x; As[(akq0 + 2) * 4 + 1][ar] = pa1.y;
        As[(akq0 + 2) * 4 + 2][ar] = pa1.z; As[(akq0 + 2) * 4 + 3][ar] = pa1.w;
        float4 d0 = make_float4(pb.x, pb.x, pb.y, pb.y);
        float4 d1 = make_float4(pb.z, pb.z, pb.w, pb.w);
        *(float4*)&Bs2[bkk][bnq * 8]     = d0;
        *(float4*)&Bs2[bkk][bnq * 8 + 4] = d1;
        __syncthreads();
        if (c + 1 < NC) {
            pa0 = *(const float4*)(aptr0 + (c + 1) * 16);
            pa1 = *(const float4*)(aptr1 + (c + 1) * 16);
            pb  = *(const float4*)(bptr + (size_t)(c + 1) * 16 * NZ);
        }
#pragma unroll
        for (int kk = 0; kk < 16; kk++) {
            ulonglong2 a01 = *(const ulonglong2*)&As[kk][ty * 8];      // rowpairs 0,1
            ulonglong2 a23 = *(const ulonglong2*)&As[kk][ty * 8 + 4];  // rowpairs 2,3
            ulonglong2 bA  = *(const ulonglong2*)&Bs2[kk][tx * 8];     // cols 0,1 (dup)
            ulonglong2 bB  = *(const ulonglong2*)&Bs2[kk][tx * 8 + 4]; // cols 2,3 (dup)
            acc2[0][0] = ffma2_(a01.x, bA.x, acc2[0][0]);
            acc2[0][1] = ffma2_(a01.x, bA.y, acc2[0][1]);
            acc2[0][2] = ffma2_(a01.x, bB.x, acc2[0][2]);
            acc2[0][3] = ffma2_(a01.x, bB.y, acc2[0][3]);
            acc2[1][0] = ffma2_(a01.y, bA.x, acc2[1][0]);
            acc2[1][1] = ffma2_(a01.y, bA.y, acc2[1][1]);
            acc2[1][2] = ffma2_(a01.y, bB.x, acc2[1][2]);
            acc2[1][3] = ffma2_(a01.y, bB.y, acc2[1][3]);
            acc2[2][0] = ffma2_(a23.x, bA.x, acc2[2][0]);
            acc2[2][1] = ffma2_(a23.x, bA.y, acc2[2][1]);
            acc2[2][2] = ffma2_(a23.x, bB.x, acc2[2][2]);
            acc2[2][3] = ffma2_(a23.x, bB.y, acc2[2][3]);
            acc2[3][0] = ffma2_(a23.y, bA.x, acc2[3][0]);
            acc2[3][1] = ffma2_(a23.y, bA.y, acc2[3][1]);
            acc2[3][2] = ffma2_(a23.y, bB.x, acc2[3][2]);
            acc2[3][3] = ffma2_(a23.y, bB.y, acc2[3][3]);
        }
        __syncthreads();
    }
#pragma unroll
    for (int rp = 0; rp < 4; rp++) {
#pragma unroll
        for (int cc = 0; cc < 4; cc++) {
            float2 v = unpack2_(acc2[rp][cc]);
            int n = n0 + tx * 4 + cc;
            int r = row0 + ty * 8 + rp * 2;
            float bv = b0[n];
            g_P0[(size_t)r * NZ + n]       = v.x + bv;
            g_P0[(size_t)(r + 1) * NZ + n] = v.y + bv;
        }
    }
}

__device__ __forceinline__ float sigmoidf_(float v) {
    return 1.f / (1.f + __expf(-v));
}

// ---------------------------------------------------------------------------
// software grid barrier (all NBLK blocks co-resident)
// ---------------------------------------------------------------------------
__device__ __forceinline__ void grid_sync_() {
    __syncthreads();
    if (threadIdx.x == 0) {
        __threadfence();
        unsigned gen = g_gen;
        if (atomicAdd(&g_count, 1u) == NBLK - 1) {
            g_count = 0;
            __threadfence();
            g_gen = gen + 1;
        } else {
            while (g_gen == gen) { }
        }
        __threadfence();
    }
    __syncthreads();
}

// ---------------------------------------------------------------------------
// k_rnn: entire 512-step recurrence in ONE persistent kernel.
// 128 blocks x 512 threads (16 warps/SM). Block owns 8 hidden units x 4
// gates = 32 z-cols. Thread = 1 batch row x 4 gates of one unit
// (jj = tid&7, row = tid>>3). c-state in registers. FFMA2 inner loop with
// A duplicated in smem ({h,h} pairs) so one LDS.64 feeds both lanes.
// ---------------------------------------------------------------------------
__global__ __launch_bounds__(512) void k_rnn(const float* __restrict__ U0,
                                             const float* __restrict__ W1,
                                             const float* __restrict__ U1,
                                             const float* __restrict__ b1) {
    __shared__ float2 As2[KC][64];   // duplicated h: [k][row] = {h,h}
    __shared__ float  Bs[KC][32];    // [k][jj*4 + gate]
    int tid = threadIdx.x;
    int jj = tid & 7, row = tid >> 3;        // row 0..63
    int j0 = blockIdx.x * 8;
    int j = j0 + jj;

    // A loader: thread loads float4 of h for row lar, k-quad laq (8 quads = 32 k)
    int lar = tid & 63, laq = tid >> 6;      // laq 0..7
    // B loader: e0 = tid covers k 0..15, e1 = tid+512 covers k 16..31
    int bjj0 = tid & 7, bg0 = (tid >> 3) & 3, bkk0 = tid >> 5;
    int e1 = tid + 512;
    int bjj1 = e1 & 7, bg1 = (e1 >> 3) & 3, bkk1 = e1 >> 5;
    size_t bOff0 = (size_t)bkk0 * NZ + (size_t)bg0 * NH + j0 + bjj0;
    size_t bOff1 = (size_t)bkk1 * NZ + (size_t)bg1 * NH + j0 + bjj1;

    float c0reg = 0.f, c1reg = 0.f;
    float b1g0 = b1[j], b1g1 = b1[NH + j], b1g2 = b1[2 * NH + j], b1g3 = b1[3 * NH + j];

    for (int t = 0; t < NT; t++) {
        const float* h0r = g_h0 + (size_t)(t & 1) * SH;
        float*       h0w = g_h0 + (size_t)((t & 1) ^ 1) * SH;
        const float* h1r = g_h1 + (size_t)(t & 1) * SH;
        float*       h1w = g_h1 + (size_t)((t & 1) ^ 1) * SH;

        // ================= phase A: z0 = P0[t] + h0r @ U0 (K=1024) =========
        {
            ull acc01 = 0ull, acc23 = 0ull;
            float4 pa = *(const float4*)(h0r + (size_t)lar * NH + laq * 4);
            float pb0 = U0[bOff0];
            float pb1 = U0[bOff1];
            const int NCA = NH / KC;
            for (int c = 0; c < NCA; c++) {
                As2[laq * 4 + 0][lar] = make_float2(pa.x, pa.x);
                As2[laq * 4 + 1][lar] = make_float2(pa.y, pa.y);
                As2[laq * 4 + 2][lar] = make_float2(pa.z, pa.z);
                As2[laq * 4 + 3][lar] = make_float2(pa.w, pa.w);
                Bs[bkk0][bjj0 * 4 + bg0] = pb0;
                Bs[bkk1][bjj1 * 4 + bg1] = pb1;
                __syncthreads();
                if (c + 1 < NCA) {
                    int k0n = (c + 1) * KC;
                    pa  = *(const float4*)(h0r + (size_t)lar * NH + k0n + laq * 4);
                    pb0 = U0[bOff0 + (size_t)k0n * NZ];
                    pb1 = U0[bOff1 + (size_t)k0n * NZ];
                }
#pragma unroll
                for (int kk = 0; kk < KC; kk++) {
                    ull a2 = *(const ull*)&As2[kk][row];
                    ulonglong2 b2 = *(const ulonglong2*)&Bs[kk][jj * 4];
                    acc01 = ffma2_(a2, b2.x, acc01);
                    acc23 = ffma2_(a2, b2.y, acc23);
                }
                __syncthreads();
            }
            float2 v01 = unpack2_(acc01);
            float2 v23 = unpack2_(acc23);
            size_t pbase = ((size_t)t * NB + row) * NZ;
            float zi = v01.x + g_P0[pbase + j];
            float zf = v01.y + g_P0[pbase + NH + j];
            float zc = v23.x + g_P0[pbase + 2 * NH + j];
            float zo = v23.y + g_P0[pbase + 3 * NH + j];
            float cv = sigmoidf_(zf) * c0reg + sigmoidf_(zi) * tanhf(zc);
            c0reg = cv;
            h0w[row * NH + j] = sigmoidf_(zo) * tanhf(cv);
        }
        grid_sync_();

        // ========== phase B: z1 = h0w @ W1 + h1r @ U1 + b1 (K=2048) ========
        {
            ull acc01 = 0ull, acc23 = 0ull;
            float4 pa = *(const float4*)(h0w + (size_t)lar * NH + laq * 4);
            float pb0 = W1[bOff0];
            float pb1 = W1[bOff1];
            const int NCB = (2 * NH) / KC;
            for (int c = 0; c < NCB; c++) {
                As2[laq * 4 + 0][lar] = make_float2(pa.x, pa.x);
                As2[laq * 4 + 1][lar] = make_float2(pa.y, pa.y);
                As2[laq * 4 + 2][lar] = make_float2(pa.z, pa.z);
                As2[laq * 4 + 3][lar] = make_float2(pa.w, pa.w);
                Bs[bkk0][bjj0 * 4 + bg0] = pb0;
                Bs[bkk1][bjj1 * 4 + bg1] = pb1;
                __syncthreads();
                if (c + 1 < NCB) {
                    int k0n = (c + 1) * KC;
                    const float* srcA = (k0n < NH) ? h0w : h1r;
                    const float* srcB = (k0n < NH) ? W1 : U1;
                    int koff = k0n & (NH - 1);
                    pa  = *(const float4*)(srcA + (size_t)lar * NH + koff + laq * 4);
                    pb0 = srcB[bOff0 + (size_t)koff * NZ];
                    pb1 = srcB[bOff1 + (size_t)koff * NZ];
                }
#pragma unroll
                for (int kk = 0; kk < KC; kk++) {
                    ull a2 = *(const ull*)&As2[kk][row];
                    ulonglong2 b2 = *(const ulonglong2*)&Bs[kk][jj * 4];
                    acc01 = ffma2_(a2, b2.x, acc01);
                    acc23 = ffma2_(a2, b2.y, acc23);
                }
                __syncthreads();
            }
            float2 v01 = unpack2_(acc01);
            float2 v23 = unpack2_(acc23);
            float zi = v01.x + b1g0;
            float zf = v01.y + b1g1;
            float zc = v23.x + b1g2;
            float zo = v23.y + b1g3;
            float cv = sigmoidf_(zf) * c1reg + sigmoidf_(zi) * tanhf(zc);
            c1reg = cv;
            h1w[row * NH + j] = sigmoidf_(zo) * tanhf(cv);
        }
        grid_sync_();
    }
}

// ---------------------------------------------------------------------------
// k_out: out = tanh( h1_final @ Wo + bo ),  [64,1024]@[1024,128]
// ---------------------------------------------------------------------------
__global__ void k_out(const float* __restrict__ Wo, const float* __restrict__ bo,
                      float* __restrict__ out) {
    int idx = blockIdx.x * blockDim.x + threadIdx.x;
    if (idx >= NB * NDOUT) return;
    int n = idx & 127, b = idx >> 7;
    const float* h = g_h1;   // final h1 lives in parity-0 buffer after T=512 steps
    float s0 = 0.f, s1 = 0.f, s2 = 0.f, s3 = 0.f;
#pragma unroll 4
    for (int k = 0; k < NH; k += 4) {
        s0 += h[b * NH + k + 0] * Wo[(size_t)(k + 0) * NDOUT + n];
        s1 += h[b * NH + k + 1] * Wo[(size_t)(k + 1) * NDOUT + n];
        s2 += h[b * NH + k + 2] * Wo[(size_t)(k + 2) * NDOUT + n];
        s3 += h[b * NH + k + 3] * Wo[(size_t)(k + 3) * NDOUT + n];
    }
    out[idx] = tanhf((s0 + s1) + (s2 + s3) + bo[n]);
}

// ---------------------------------------------------------------------------
extern "C" void kernel_launch(void* const* d_in, const int* in_sizes, int n_in,
                              void* d_out, int out_size) {
    const float* x  = (const float*)d_in[0];
    const float* Wi = (const float*)d_in[1];
    const float* bi = (const float*)d_in[2];
    const float* W0 = (const float*)d_in[3];
    const float* U0 = (const float*)d_in[4];
    const float* b0 = (const float*)d_in[5];
    const float* W1 = (const float*)d_in[6];
    const float* U1 = (const float*)d_in[7];
    const float* b1 = (const float*)d_in[8];
    const float* Wo = (const float*)d_in[9];
    const float* bo = (const float*)d_in[10];
    float* out = (float*)d_out;
    (void)in_sizes; (void)n_in; (void)out_size;

    k_init<<<512, 256>>>();
    k_xin<<<dim3(16, 512), 256>>>(x, Wi, bi);
    k_p0<<<dim3(64, 256), 256>>>(W0, b0);
    k_rnn<<<NBLK, 512>>>(U0, W1, U1, b1);
    k_out<<<32, 256>>>(Wo, bo, out);
}

// round 7
// speedup vs baseline: 1.8955x; 1.8955x over previous
#include <cuda_runtime.h>
#include <stdint.h>
#include <math.h>

#define NB 64
#define NT 512
#define NF 512
#define NDIN 1024
#define NH 1024
#define NZ 4096
#define NDOUT 128
#define SH (NB*NH)     // 65536 floats per h buffer
#define NBLK 128       // persistent blocks (1/SM, all co-resident)
#define KCH 32         // k per cp.async chunk in k_rnn

typedef unsigned long long ull;

// Scratch (device globals; no dynamic allocation allowed)
__device__ float g_xin[(size_t)NT * NB * NDIN];   // tanh(x@Wi+bi), rows r = t*NB+b
__device__ float g_P0[(size_t)NT * NB * NZ];      // xin@W0 + b0
__device__ float g_h0T[2 * SH];                   // transposed h0: [par][j][64 rows]
__device__ float g_h1T[2 * SH];                   // transposed h1
// packed, duplicated recurrent weights, block-major:
// g_WA[(bid*1024 + k)*32 + lane] = {U0[k][g*NH + bid*8+u], same}, lane = g*8+u
__device__ float2 g_WA[(size_t)NBLK * 1024 * 32];   // 32 MB
// g_WB: k<1024 -> W1, k>=1024 -> U1, same packing. [(bid*2048 + k)*32 + lane]
__device__ float2 g_WB[(size_t)NBLK * 2048 * 32];   // 64 MB

// grid barrier state
__device__ unsigned g_count;
__device__ volatile unsigned g_gen;

// ---------------------------------------------------------------------------
// packed f32x2 helpers (sm_103a dual-fp32 pipe, PTX-only)
// ---------------------------------------------------------------------------
__device__ __forceinline__ ull ffma2_(ull a, ull b, ull c) {
    ull d;
    asm("fma.rn.f32x2 %0, %1, %2, %3;" : "=l"(d) : "l"(a), "l"(b), "l"(c));
    return d;
}
__device__ __forceinline__ float2 unpack2_(ull v) {
    float2 r;
    asm("mov.b64 {%0, %1}, %2;" : "=f"(r.x), "=f"(r.y) : "l"(v));
    return r;
}

// cp.async, L2-only (.cg) — bypasses L1 so cross-SM h updates are never stale
__device__ __forceinline__ void cp16_(uint32_t dst, const void* src) {
    asm volatile("cp.async.cg.shared.global [%0], [%1], 16;" :: "r"(dst), "l"(src));
}
#define CPCOMMIT() asm volatile("cp.async.commit_group;" ::: "memory")
#define CPWAIT1()  asm volatile("cp.async.wait_group 1;"  ::: "memory")

__device__ __forceinline__ float sigmoidf_(float v) {
    return 1.f / (1.f + __expf(-v));
}

// ---------------------------------------------------------------------------
__global__ void k_init() {
    int idx = blockIdx.x * blockDim.x + threadIdx.x;
    if (idx < 2 * SH) { g_h0T[idx] = 0.f; g_h1T[idx] = 0.f; }
    if (idx == 0) { g_count = 0; g_gen = 0; }
}

// ---------------------------------------------------------------------------
// k_prep: pack + duplicate recurrent weights into block-major streams.
// ---------------------------------------------------------------------------
__global__ void k_prep(const float* __restrict__ U0, const float* __restrict__ W1,
                       const float* __restrict__ U1) {
    int idx = blockIdx.x * blockDim.x + threadIdx.x;
    const int NWA = NBLK * 1024 * 32;      // 4M
    const int NWB = NBLK * 2048 * 32;      // 8M
    if (idx < NWA) {
        int l = idx & 31, k = (idx >> 5) & 1023, b = idx >> 15;
        int u = l & 7, g = l >> 3;
        float v = U0[(size_t)k * NZ + g * NH + b * 8 + u];
        g_WA[idx] = make_float2(v, v);
    }
    if (idx < NWB) {
        int l = idx & 31, k = (idx >> 5) & 2047, b = idx >> 16;
        int u = l & 7, g = l >> 3;
        float v = (k < 1024) ? W1[(size_t)k * NZ + g * NH + b * 8 + u]
                             : U1[(size_t)(k - 1024) * NZ + g * NH + b * 8 + u];
        g_WB[idx] = make_float2(v, v);
    }
}

// ---------------------------------------------------------------------------
// k_xin: xin[r, n] = tanh( x[b,t,:] @ Wi[:,n] + bi[n] ),  r = t*NB + b
// ---------------------------------------------------------------------------
__global__ __launch_bounds__(256) void k_xin(const float* __restrict__ x,
                                             const float* __restrict__ Wi,
                                             const float* __restrict__ bi) {
    __shared__ float As[16][64];
    __shared__ float Bs[16][64];
    int tid = threadIdx.x;
    int tx = tid & 15, ty = tid >> 4;
    int n0 = blockIdx.x * 64;
    int row0 = blockIdx.y * 64;

    float acc[4][4] = {};

    int ar = tid & 63, akq = tid >> 6;
    int R = row0 + ar;
    int bb = R & 63, tt = R >> 6;               // r = t*NB + b
    const float* aptr = x + ((size_t)bb * NT + tt) * NF + akq * 4;
    int bkk = tid >> 4, bnq = tid & 15;
    const float* bptr = Wi + (size_t)bkk * NDIN + n0 + bnq * 4;

    float4 pa = *(const float4*)aptr;
    float4 pb = *(const float4*)bptr;

    const int NC = NF / 16;
    for (int c = 0; c < NC; c++) {
        As[akq * 4 + 0][ar] = pa.x; As[akq * 4 + 1][ar] = pa.y;
        As[akq * 4 + 2][ar] = pa.z; As[akq * 4 + 3][ar] = pa.w;
        *(float4*)&Bs[bkk][bnq * 4] = pb;
        __syncthreads();
        if (c + 1 < NC) {
            pa = *(const float4*)(aptr + (c + 1) * 16);
            pb = *(const float4*)(bptr + (size_t)(c + 1) * 16 * NDIN);
        }
#pragma unroll
        for (int kk = 0; kk < 16; kk++) {
            float4 a = *(const float4*)&As[kk][ty * 4];
            float4 b = *(const float4*)&Bs[kk][tx * 4];
            acc[0][0] += a.x * b.x; acc[0][1] += a.x * b.y; acc[0][2] += a.x * b.z; acc[0][3] += a.x * b.w;
            acc[1][0] += a.y * b.x; acc[1][1] += a.y * b.y; acc[1][2] += a.y * b.z; acc[1][3] += a.y * b.w;
            acc[2][0] += a.z * b.x; acc[2][1] += a.z * b.y; acc[2][2] += a.z * b.z; acc[2][3] += a.z * b.w;
            acc[3][0] += a.w * b.x; acc[3][1] += a.w * b.y; acc[3][2] += a.w * b.z; acc[3][3] += a.w * b.w;
        }
        __syncthreads();
    }
#pragma unroll
    for (int i = 0; i < 4; i++) {
        int r = row0 + ty * 4 + i;
#pragma unroll
        for (int jx = 0; jx < 4; jx++) {
            int n = n0 + tx * 4 + jx;
            g_xin[(size_t)r * NDIN + n] = tanhf(acc[i][jx] + bi[n]);
        }
    }
}

// ---------------------------------------------------------------------------
// k_p0: P0 = xin @ W0 + b0.  GEMM M=32768, K=1024, N=4096. (round-4 version)
// ---------------------------------------------------------------------------
__global__ __launch_bounds__(256) void k_p0(const float* __restrict__ W0,
                                            const float* __restrict__ b0) {
    __shared__ float As[16][128];
    __shared__ float Bs[16][64];
    int tid = threadIdx.x;
    int tx = tid & 15, ty = tid >> 4;
    int n0 = blockIdx.x * 64;
    int row0 = blockIdx.y * 128;

    float acc[8][4] = {};

    int ar = tid & 127, akq0 = tid >> 7;
    const float* aptr0 = g_xin + (size_t)(row0 + ar) * NDIN + akq0 * 4;
    const float* aptr1 = g_xin + (size_t)(row0 + ar) * NDIN + (akq0 + 2) * 4;
    int bkk = tid >> 4, bnq = tid & 15;
    const float* bptr = W0 + (size_t)bkk * NZ + n0 + bnq * 4;

    float4 pa0 = *(const float4*)aptr0;
    float4 pa1 = *(const float4*)aptr1;
    float4 pb  = *(const float4*)bptr;

    const int NC = NDIN / 16;
    for (int c = 0; c < NC; c++) {
        As[akq0 * 4 + 0][ar] = pa0.x; As[akq0 * 4 + 1][ar] = pa0.y;
        As[akq0 * 4 + 2][ar] = pa0.z; As[akq0 * 4 + 3][ar] = pa0.w;
        As[(akq0 + 2) * 4 + 0][ar] = pa1.x; As[(akq0 + 2) * 4 + 1][ar] = pa1.y;
        As[(akq0 + 2) * 4 + 2][ar] = pa1.z; As[(akq0 + 2) * 4 + 3][ar] = pa1.w;
        *(float4*)&Bs[bkk][bnq * 4] = pb;
        __syncthreads();
        if (c + 1 < NC) {
            pa0 = *(const float4*)(aptr0 + (c + 1) * 16);
            pa1 = *(const float4*)(aptr1 + (c + 1) * 16);
            pb  = *(const float4*)(bptr + (size_t)(c + 1) * 16 * NZ);
        }
#pragma unroll
        for (int kk = 0; kk < 16; kk++) {
            float4 a0 = *(const float4*)&As[kk][ty * 8];
            float4 a1 = *(const float4*)&As[kk][ty * 8 + 4];
            float4 b  = *(const float4*)&Bs[kk][tx * 4];
            acc[0][0] += a0.x * b.x; acc[0][1] += a0.x * b.y; acc[0][2] += a0.x * b.z; acc[0][3] += a0.x * b.w;
            acc[1][0] += a0.y * b.x; acc[1][1] += a0.y * b.y; acc[1][2] += a0.y * b.z; acc[1][3] += a0.y * b.w;
            acc[2][0] += a0.z * b.x; acc[2][1] += a0.z * b.y; acc[2][2] += a0.z * b.z; acc[2][3] += a0.z * b.w;
            acc[3][0] += a0.w * b.x; acc[3][1] += a0.w * b.y; acc[3][2] += a0.w * b.z; acc[3][3] += a0.w * b.w;
            acc[4][0] += a1.x * b.x; acc[4][1] += a1.x * b.y; acc[4][2] += a1.x * b.z; acc[4][3] += a1.x * b.w;
            acc[5][0] += a1.y * b.x; acc[5][1] += a1.y * b.y; acc[5][2] += a1.y * b.z; acc[5][3] += a1.y * b.w;
            acc[6][0] += a1.z * b.x; acc[6][1] += a1.z * b.y; acc[6][2] += a1.z * b.z; acc[6][3] += a1.z * b.w;
            acc[7][0] += a1.w * b.x; acc[7][1] += a1.w * b.y; acc[7][2] += a1.w * b.z; acc[7][3] += a1.w * b.w;
        }
        __syncthreads();
    }
#pragma unroll
    for (int i = 0; i < 8; i++) {
        int r = row0 + ty * 8 + i;
#pragma unroll
        for (int jx = 0; jx < 4; jx++) {
            int n = n0 + tx * 4 + jx;
            g_P0[(size_t)r * NZ + n] = acc[i][jx] + b0[n];
        }
    }
}

// ---------------------------------------------------------------------------
// software grid barrier (all NBLK blocks co-resident)
// ---------------------------------------------------------------------------
__device__ __forceinline__ void grid_sync_() {
    __syncthreads();
    if (threadIdx.x == 0) {
        __threadfence();
        unsigned gen = g_gen;
        if (atomicAdd(&g_count, 1u) == NBLK - 1) {
            g_count = 0;
            __threadfence();
            g_gen = gen + 1;
        } else {
            while (g_gen == gen) { }
        }
        __threadfence();
    }
    __syncthreads();
}

// ---------------------------------------------------------------------------
// 4x4 register transpose among lanes {u, u+8, u+16, u+24} (bits 3,4 of lane).
// Before: lane (u,g) holds acc[s] = z[rowpair s][gate g].
// After:  lane (u,g) holds acc[s] = z[rowpair g][gate s].
// ---------------------------------------------------------------------------
__device__ __forceinline__ void transpose4_(ull acc[4], int g) {
    ull x0 = (g & 1) ? acc[0] : acc[1];
    ull x1 = (g & 1) ? acc[2] : acc[3];
    x0 = __shfl_xor_sync(0xffffffffu, x0, 8);
    x1 = __shfl_xor_sync(0xffffffffu, x1, 8);
    if (g & 1) { acc[0] = x0; acc[2] = x1; } else { acc[1] = x0; acc[3] = x1; }
    x0 = (g & 2) ? acc[0] : acc[2];
    x1 = (g & 2) ? acc[1] : acc[3];
    x0 = __shfl_xor_sync(0xffffffffu, x0, 16);
    x1 = __shfl_xor_sync(0xffffffffu, x1, 16);
    if (g & 2) { acc[0] = x0; acc[1] = x1; } else { acc[2] = x0; acc[3] = x1; }
}

// ---------------------------------------------------------------------------
// one GEMM phase: acc[rp] += sum_k {hT[k][2rp],hT[k][2rp+1]} * {w,w}
// h streamed via cp.async.cg chunks (contiguous hT), weights likewise.
// ---------------------------------------------------------------------------
__device__ __forceinline__ void run_phase_(
    ull acc[4], const float* hA, const float* hB, int ncA, int ncTot,
    const float2* wbase, int tid, int rowbase, int lane,
    uint32_t hs_s, uint32_t ws_s,
    float (&hs)[2][KCH][64], float2 (&ws)[2][KCH][32])
{
    auto hsrc = [&](int c) {
        return (c < ncA) ? hA + (size_t)c * KCH * 64
                         : hB + (size_t)(c - ncA) * KCH * 64;
    };
    auto load = [&](int buf, int c) {
        const char* hp = (const char*)hsrc(c) + tid * 16;
        uint32_t hd = hs_s + buf * 8192 + tid * 16;
        cp16_(hd, hp); cp16_(hd + 4096, hp + 4096);
        const char* wp = (const char*)(wbase + (size_t)c * KCH * 32) + tid * 16;
        uint32_t wd = ws_s + buf * 8192 + tid * 16;
        cp16_(wd, wp); cp16_(wd + 4096, wp + 4096);
    };

    load(0, 0); CPCOMMIT();
    load(1, 1); CPCOMMIT();
    CPWAIT1();
    __syncthreads();

    for (int c = 0; c < ncTot; c++) {
        int buf = c & 1;
#pragma unroll 8
        for (int kk = 0; kk < KCH; kk++) {
            ulonglong2 h01 = *(const ulonglong2*)&hs[buf][kk][rowbase];
            ulonglong2 h23 = *(const ulonglong2*)&hs[buf][kk][rowbase + 4];
            ull wd = *(const ull*)&ws[buf][kk][lane];
            acc[0] = ffma2_(h01.x, wd, acc[0]);
            acc[1] = ffma2_(h01.y, wd, acc[1]);
            acc[2] = ffma2_(h23.x, wd, acc[2]);
            acc[3] = ffma2_(h23.y, wd, acc[3]);
        }
        __syncthreads();
        if (c + 2 < ncTot) load(buf, c + 2);
        CPCOMMIT();
        CPWAIT1();
        __syncthreads();
    }
}

// ---------------------------------------------------------------------------
// k_rnn: entire 512-step recurrence, one persistent kernel.
// 128 blocks x 256 threads. Block owns 8 hidden units (32 z-cols).
// Warp = 32 cols x 8 rows; lane (u = lane&7, g = lane>>3) accumulates
// column (unit u, gate g) over its warp's 8 rows as 4 packed FFMA2 accs.
// hT smem reads are warp-broadcast; weights pre-duplicated {w,w}.
// ---------------------------------------------------------------------------
__global__ __launch_bounds__(256, 1) void k_rnn(const float* __restrict__ b1) {
    __shared__ __align__(16) float  hs[2][KCH][64];
    __shared__ __align__(16) float2 ws[2][KCH][32];

    int tid = threadIdx.x;
    int w = tid >> 5, lane = tid & 31;
    int u = lane & 7, g = lane >> 3;
    int rowbase = w * 8;
    int row_lo = rowbase + 2 * g;
    int bid = blockIdx.x;
    int j = bid * 8 + u;

    uint32_t hs_s = (uint32_t)__cvta_generic_to_shared(&hs[0][0][0]);
    uint32_t ws_s = (uint32_t)__cvta_generic_to_shared(&ws[0][0][0]);

    const float2* wA = g_WA + (size_t)bid * 1024 * 32;
    const float2* wB = g_WB + (size_t)bid * 2048 * 32;

    float b10 = b1[j], b11 = b1[NH + j], b12 = b1[2 * NH + j], b13 = b1[3 * NH + j];
    float c0l = 0.f, c0h = 0.f, c1l = 0.f, c1h = 0.f;

    for (int t = 0; t < NT; t++) {
        int par = t & 1;
        const float* h0r = g_h0T + (size_t)par * SH;
        float*       h0w = g_h0T + (size_t)(par ^ 1) * SH;
        const float* h1r = g_h1T + (size_t)par * SH;
        float*       h1w = g_h1T + (size_t)(par ^ 1) * SH;

        // prefetch P0 for this step's epilogue (8 scalars, latency hidden)
        size_t pb = ((size_t)t * NB + row_lo) * NZ + j;
        float p0l = g_P0[pb],            p1l = g_P0[pb + NH];
        float p2l = g_P0[pb + 2 * NH],   p3l = g_P0[pb + 3 * NH];
        float p0h = g_P0[pb + NZ],           p1h = g_P0[pb + NZ + NH];
        float p2h = g_P0[pb + NZ + 2 * NH],  p3h = g_P0[pb + NZ + 3 * NH];

        // ===== phase A: z0 = P0[t] + h0 @ U0 (K = 1024) =====
        {
            ull acc[4] = {0ull, 0ull, 0ull, 0ull};
            run_phase_(acc, h0r, h0r, 32, 32, wA, tid, rowbase, lane, hs_s, ws_s, hs, ws);
            transpose4_(acc, g);
            float2 z0 = unpack2_(acc[0]), z1 = unpack2_(acc[1]);
            float2 z2 = unpack2_(acc[2]), z3 = unpack2_(acc[3]);
            float il = sigmoidf_(z0.x + p0l), fl = sigmoidf_(z1.x + p1l);
            float gl = tanhf(z2.x + p2l),     ol = sigmoidf_(z3.x + p3l);
            c0l = fl * c0l + il * gl;
            float hl = ol * tanhf(c0l);
            float ih = sigmoidf_(z0.y + p0h), fh = sigmoidf_(z1.y + p1h);
            float gh = tanhf(z2.y + p2h),     oh = sigmoidf_(z3.y + p3h);
            c0h = fh * c0h + ih * gh;
            float hh = oh * tanhf(c0h);
            *(float2*)&h0w[j * 64 + row_lo] = make_float2(hl, hh);
        }
        grid_sync_();

        // ===== phase B: z1 = h0_new @ W1 + h1 @ U1 + b1 (K = 2048) =====
        {
            ull acc[4] = {0ull, 0ull, 0ull, 0ull};
            run_phase_(acc, h0w, h1r, 32, 64, wB, tid, rowbase, lane, hs_s, ws_s, hs, ws);
            transpose4_(acc, g);
            float2 z0 = unpack2_(acc[0]), z1 = unpack2_(acc[1]);
            float2 z2 = unpack2_(acc[2]), z3 = unpack2_(acc[3]);
            float il = sigmoidf_(z0.x + b10), fl = sigmoidf_(z1.x + b11);
            float gl = tanhf(z2.x + b12),     ol = sigmoidf_(z3.x + b13);
            c1l = fl * c1l + il * gl;
            float hl = ol * tanhf(c1l);
            float ih = sigmoidf_(z0.y + b10), fh = sigmoidf_(z1.y + b11);
            float gh = tanhf(z2.y + b12),     oh = sigmoidf_(z3.y + b13);
            c1h = fh * c1h + ih * gh;
            float hh = oh * tanhf(c1h);
            *(float2*)&h1w[j * 64 + row_lo] = make_float2(hl, hh);
        }
        grid_sync_();
    }
}

// ---------------------------------------------------------------------------
// k_out: out = tanh( h1_final @ Wo + bo ),  h1 stored transposed hT[k][b]
// ---------------------------------------------------------------------------
__global__ void k_out(const float* __restrict__ Wo, const float* __restrict__ bo,
                      float* __restrict__ out) {
    int idx = blockIdx.x * blockDim.x + threadIdx.x;
    if (idx >= NB * NDOUT) return;
    int n = idx & 127, b = idx >> 7;
    const float* hT = g_h1T;   // final h1 at parity 0 after T=512 steps
    float s0 = 0.f, s1 = 0.f, s2 = 0.f, s3 = 0.f;
#pragma unroll 4
    for (int k = 0; k < NH; k += 4) {
        s0 += hT[(k + 0) * 64 + b] * Wo[(size_t)(k + 0) * NDOUT + n];
        s1 += hT[(k + 1) * 64 + b] * Wo[(size_t)(k + 1) * NDOUT + n];
        s2 += hT[(k + 2) * 64 + b] * Wo[(size_t)(k + 2) * NDOUT + n];
        s3 += hT[(k + 3) * 64 + b] * Wo[(size_t)(k + 3) * NDOUT + n];
    }
    out[idx] = tanhf((s0 + s1) + (s2 + s3) + bo[n]);
}

// ---------------------------------------------------------------------------
extern "C" void kernel_launch(void* const* d_in, const int* in_sizes, int n_in,
                              void* d_out, int out_size) {
    const float* x  = (const float*)d_in[0];
    const float* Wi = (const float*)d_in[1];
    const float* bi = (const float*)d_in[2];
    const float* W0 = (const float*)d_in[3];
    const float* U0 = (const float*)d_in[4];
    const float* b0 = (const float*)d_in[5];
    const float* W1 = (const float*)d_in[6];
    const float* U1 = (const float*)d_in[7];
    const float* b1 = (const float*)d_in[8];
    const float* Wo = (const float*)d_in[9];
    const float* bo = (const float*)d_in[10];
    float* out = (float*)d_out;
    (void)in_sizes; (void)n_in; (void)out_size;

    k_init<<<512, 256>>>();
    k_prep<<<32768, 256>>>(U0, W1, U1);
    k_xin<<<dim3(16, 512), 256>>>(x, Wi, bi);
    k_p0<<<dim3(64, 256), 256>>>(W0, b0);
    k_rnn<<<NBLK, 256>>>(b1);
    k_out<<<32, 256>>>(Wo, bo, out);
}

// round 9
// speedup vs baseline: 2.1364x; 1.1271x over previous
#include <cuda_runtime.h>
#include <stdint.h>
#include <math.h>

#define NB 64
#define NT 512
#define NF 512
#define NDIN 1024
#define NH 1024
#define NZ 4096
#define NDOUT 128
#define SH (NB*NH)     // 65536 floats per h buffer
#define NBLK 128       // persistent blocks (1/SM, all co-resident)
#define KCH 32         // k per chunk in k_rnn

typedef unsigned long long ull;

// Scratch (device globals; no dynamic allocation allowed)
__device__ float g_xin[(size_t)NT * NB * NDIN];   // tanh(x@Wi+bi), rows r = t*NB+b
__device__ float g_P0[(size_t)NT * NB * NZ];      // xin@W0 + b0
__device__ float g_h0T[2 * SH];                   // transposed h0: [par][j][64 rows]
__device__ float g_h1T[2 * SH];                   // transposed h1
// packed recurrent weights (NOT duplicated), block-major:
// g_WA[bid*1024*32 + k*32 + lane] = U0[k][g*NH + bid*8+u], lane = g*8+u
__device__ float g_WA[(size_t)NBLK * 1024 * 32];    // 16 MB
// g_WB: k<1024 -> W1[k], k>=1024 -> U1[k-1024], same per-k lane packing
__device__ float g_WB[(size_t)NBLK * 2048 * 32];    // 32 MB

// grid barrier state
__device__ unsigned g_count;
__device__ volatile unsigned g_gen;

// ---------------------------------------------------------------------------
// packed f32x2 helpers (sm_103a dual-fp32 pipe, PTX-only)
// ---------------------------------------------------------------------------
__device__ __forceinline__ ull ffma2_(ull a, ull b, ull c) {
    ull d;
    asm("fma.rn.f32x2 %0, %1, %2, %3;" : "=l"(d) : "l"(a), "l"(b), "l"(c));
    return d;
}
__device__ __forceinline__ ull addf2_(ull a, ull b) {
    ull d;
    asm("add.rn.f32x2 %0, %1, %2;" : "=l"(d) : "l"(a), "l"(b));
    return d;
}
__device__ __forceinline__ float2 unpack2_(ull v) {
    float2 r;
    asm("mov.b64 {%0, %1}, %2;" : "=f"(r.x), "=f"(r.y) : "l"(v));
    return r;
}

// cp.async, L2-only (.cg) — bypasses L1 so cross-SM h updates are never stale
__device__ __forceinline__ void cp16_(uint32_t dst, const void* src) {
    asm volatile("cp.async.cg.shared.global [%0], [%1], 16;" :: "r"(dst), "l"(src));
}
#define CPCOMMIT() asm volatile("cp.async.commit_group;" ::: "memory")
#define CPWAIT1()  asm volatile("cp.async.wait_group 1;"  ::: "memory")

__device__ __forceinline__ float sigmoidf_(float v) {
    return 1.f / (1.f + __expf(-v));
}

// ---------------------------------------------------------------------------
__global__ void k_init() {
    int idx = blockIdx.x * blockDim.x + threadIdx.x;
    if (idx < 2 * SH) { g_h0T[idx] = 0.f; g_h1T[idx] = 0.f; }
    if (idx == 0) { g_count = 0; g_gen = 0; }
}

// ---------------------------------------------------------------------------
// k_prep: pack recurrent weights into block-major lane streams.
// ---------------------------------------------------------------------------
__global__ void k_prep(const float* __restrict__ U0, const float* __restrict__ W1,
                       const float* __restrict__ U1) {
    int idx = blockIdx.x * blockDim.x + threadIdx.x;
    const int NWA = NBLK * 1024 * 32;      // 4M
    const int NWB = NBLK * 2048 * 32;      // 8M
    if (idx < NWA) {
        int l = idx & 31, k = (idx >> 5) & 1023, b = idx >> 15;
        int u = l & 7, g = l >> 3;
        g_WA[idx] = U0[(size_t)k * NZ + g * NH + b * 8 + u];
    }
    if (idx < NWB) {
        int l = idx & 31, k = (idx >> 5) & 2047, b = idx >> 16;
        int u = l & 7, g = l >> 3;
        g_WB[idx] = (k < 1024) ? W1[(size_t)k * NZ + g * NH + b * 8 + u]
                               : U1[(size_t)(k - 1024) * NZ + g * NH + b * 8 + u];
    }
}

// ---------------------------------------------------------------------------
// k_xin: xin[r, n] = tanh( x[b,t,:] @ Wi[:,n] + bi[n] ),  r = t*NB + b
// ---------------------------------------------------------------------------
__global__ __launch_bounds__(256) void k_xin(const float* __restrict__ x,
                                             const float* __restrict__ Wi,
                                             const float* __restrict__ bi) {
    __shared__ float As[16][64];
    __shared__ float Bs[16][64];
    int tid = threadIdx.x;
    int tx = tid & 15, ty = tid >> 4;
    int n0 = blockIdx.x * 64;
    int row0 = blockIdx.y * 64;

    float acc[4][4] = {};

    int ar = tid & 63, akq = tid >> 6;
    int R = row0 + ar;
    int bb = R & 63, tt = R >> 6;               // r = t*NB + b
    const float* aptr = x + ((size_t)bb * NT + tt) * NF + akq * 4;
    int bkk = tid >> 4, bnq = tid & 15;
    const float* bptr = Wi + (size_t)bkk * NDIN + n0 + bnq * 4;

    float4 pa = *(const float4*)aptr;
    float4 pb = *(const float4*)bptr;

    const int NC = NF / 16;
    for (int c = 0; c < NC; c++) {
        As[akq * 4 + 0][ar] = pa.x; As[akq * 4 + 1][ar] = pa.y;
        As[akq * 4 + 2][ar] = pa.z; As[akq * 4 + 3][ar] = pa.w;
        *(float4*)&Bs[bkk][bnq * 4] = pb;
        __syncthreads();
        if (c + 1 < NC) {
            pa = *(const float4*)(aptr + (c + 1) * 16);
            pb = *(const float4*)(bptr + (size_t)(c + 1) * 16 * NDIN);
        }
#pragma unroll
        for (int kk = 0; kk < 16; kk++) {
            float4 a = *(const float4*)&As[kk][ty * 4];
            float4 b = *(const float4*)&Bs[kk][tx * 4];
            acc[0][0] += a.x * b.x; acc[0][1] += a.x * b.y; acc[0][2] += a.x * b.z; acc[0][3] += a.x * b.w;
            acc[1][0] += a.y * b.x; acc[1][1] += a.y * b.y; acc[1][2] += a.y * b.z; acc[1][3] += a.y * b.w;
            acc[2][0] += a.z * b.x; acc[2][1] += a.z * b.y; acc[2][2] += a.z * b.z; acc[2][3] += a.z * b.w;
            acc[3][0] += a.w * b.x; acc[3][1] += a.w * b.y; acc[3][2] += a.w * b.z; acc[3][3] += a.w * b.w;
        }
        __syncthreads();
    }
#pragma unroll
    for (int i = 0; i < 4; i++) {
        int r = row0 + ty * 4 + i;
#pragma unroll
        for (int jx = 0; jx < 4; jx++) {
            int n = n0 + tx * 4 + jx;
            g_xin[(size_t)r * NDIN + n] = tanhf(acc[i][jx] + bi[n]);
        }
    }
}

// ---------------------------------------------------------------------------
// k_p0: P0 = xin @ W0 + b0. GEMM M=32768, K=1024, N=4096. FFMA2 inner
// (row pairs packed from As; B duplicated {v,v} in smem).
// ---------------------------------------------------------------------------
__global__ __launch_bounds__(256) void k_p0(const float* __restrict__ W0,
                                            const float* __restrict__ b0) {
    __shared__ float As[16][128];
    __shared__ float Bs2[16][128];   // duplicated: col c at [c*2], {v,v}
    int tid = threadIdx.x;
    int tx = tid & 15, ty = tid >> 4;
    int n0 = blockIdx.x * 64;
    int row0 = blockIdx.y * 128;

    ull acc2[4][4] = {};             // [rowpair][col]

    int ar = tid & 127, akq0 = tid >> 7;
    const float* aptr0 = g_xin + (size_t)(row0 + ar) * NDIN + akq0 * 4;
    const float* aptr1 = g_xin + (size_t)(row0 + ar) * NDIN + (akq0 + 2) * 4;
    int bkk = tid >> 4, bnq = tid & 15;
    const float* bptr = W0 + (size_t)bkk * NZ + n0 + bnq * 4;

    float4 pa0 = *(const float4*)aptr0;
    float4 pa1 = *(const float4*)aptr1;
    float4 pb  = *(const float4*)bptr;

    const int NC = NDIN / 16;
    for (int c = 0; c < NC; c++) {
        As[akq0 * 4 + 0][ar] = pa0.x; As[akq0 * 4 + 1][ar] = pa0.y;
        As[akq0 * 4 + 2][ar] = pa0.z; As[akq0 * 4 + 3][ar] = pa0.w;
        As[(akq0 + 2) * 4 + 0][ar] = pa1.x; As[(akq0 + 2) * 4 + 1][ar] = pa1.y;
        As[(akq0 + 2) * 4 + 2][ar] = pa1.z; As[(akq0 + 2) * 4 + 3][ar] = pa1.w;
        float4 d0 = make_float4(pb.x, pb.x, pb.y, pb.y);
        float4 d1 = make_float4(pb.z, pb.z, pb.w, pb.w);
        *(float4*)&Bs2[bkk][bnq * 8]     = d0;
        *(float4*)&Bs2[bkk][bnq * 8 + 4] = d1;
        __syncthreads();
        if (c + 1 < NC) {
            pa0 = *(const float4*)(aptr0 + (c + 1) * 16);
            pa1 = *(const float4*)(aptr1 + (c + 1) * 16);
            pb  = *(const float4*)(bptr + (size_t)(c + 1) * 16 * NZ);
        }
#pragma unroll
        for (int kk = 0; kk < 16; kk++) {
            ulonglong2 a01 = *(const ulonglong2*)&As[kk][ty * 8];
            ulonglong2 a23 = *(const ulonglong2*)&As[kk][ty * 8 + 4];
            ulonglong2 bA  = *(const ulonglong2*)&Bs2[kk][tx * 8];
            ulonglong2 bB  = *(const ulonglong2*)&Bs2[kk][tx * 8 + 4];
            acc2[0][0] = ffma2_(a01.x, bA.x, acc2[0][0]);
            acc2[0][1] = ffma2_(a01.x, bA.y, acc2[0][1]);
            acc2[0][2] = ffma2_(a01.x, bB.x, acc2[0][2]);
            acc2[0][3] = ffma2_(a01.x, bB.y, acc2[0][3]);
            acc2[1][0] = ffma2_(a01.y, bA.x, acc2[1][0]);
            acc2[1][1] = ffma2_(a01.y, bA.y, acc2[1][1]);
            acc2[1][2] = ffma2_(a01.y, bB.x, acc2[1][2]);
            acc2[1][3] = ffma2_(a01.y, bB.y, acc2[1][3]);
            acc2[2][0] = ffma2_(a23.x, bA.x, acc2[2][0]);
            acc2[2][1] = ffma2_(a23.x, bA.y, acc2[2][1]);
            acc2[2][2] = ffma2_(a23.x, bB.x, acc2[2][2]);
            acc2[2][3] = ffma2_(a23.x, bB.y, acc2[2][3]);
            acc2[3][0] = ffma2_(a23.y, bA.x, acc2[3][0]);
            acc2[3][1] = ffma2_(a23.y, bA.y, acc2[3][1]);
            acc2[3][2] = ffma2_(a23.y, bB.x, acc2[3][2]);
            acc2[3][3] = ffma2_(a23.y, bB.y, acc2[3][3]);
        }
        __syncthreads();
    }
#pragma unroll
    for (int rp = 0; rp < 4; rp++) {
#pragma unroll
        for (int cc = 0; cc < 4; cc++) {
            float2 v = unpack2_(acc2[rp][cc]);
            int n = n0 + tx * 4 + cc;
            int r = row0 + ty * 8 + rp * 2;
            float bv = b0[n];
            g_P0[(size_t)r * NZ + n]       = v.x + bv;
            g_P0[(size_t)(r + 1) * NZ + n] = v.y + bv;
        }
    }
}

// ---------------------------------------------------------------------------
// software grid barrier (all NBLK blocks co-resident)
// ---------------------------------------------------------------------------
__device__ __forceinline__ void grid_sync_() {
    __syncthreads();
    if (threadIdx.x == 0) {
        __threadfence();
        unsigned gen = g_gen;
        if (atomicAdd(&g_count, 1u) == NBLK - 1) {
            g_count = 0;
            __threadfence();
            g_gen = gen + 1;
        } else {
            while (g_gen == gen) { }
        }
        __threadfence();
    }
    __syncthreads();
}

// ---------------------------------------------------------------------------
// 4x4 transpose among lanes {u, u+8, u+16, u+24} (bits 3,4 of lane).
// Before: lane (u,g) holds a[m] = payload[m][g]. After: a[m] = payload[g][m].
// ---------------------------------------------------------------------------
__device__ __forceinline__ void transpose4_(ull acc[4], int g) {
    ull x0 = (g & 1) ? acc[0] : acc[1];
    ull x1 = (g & 1) ? acc[2] : acc[3];
    x0 = __shfl_xor_sync(0xffffffffu, x0, 8);
    x1 = __shfl_xor_sync(0xffffffffu, x1, 8);
    if (g & 1) { acc[0] = x0; acc[2] = x1; } else { acc[1] = x0; acc[3] = x1; }
    x0 = (g & 2) ? acc[0] : acc[2];
    x1 = (g & 2) ? acc[1] : acc[3];
    x0 = __shfl_xor_sync(0xffffffffu, x0, 16);
    x1 = __shfl_xor_sync(0xffffffffu, x1, 16);
    if (g & 2) { acc[0] = x0; acc[1] = x1; } else { acc[2] = x0; acc[3] = x1; }
}

// ---------------------------------------------------------------------------
// chunk loop: acc[s] += sum_k {hT[k][2s],hT[k][2s+1]} * {w,w}
// 16 rows per warp; weights non-dup float, duplicated in-register.
// Both K-split groups run this with identical nc (sync counts match).
// ---------------------------------------------------------------------------
__device__ __forceinline__ void chunk_loop_(
    ull acc[8], const float* hbase, const float* wbase, int nc,
    uint32_t hdst, uint32_t wdst, int gtid, int wg, int lane,
    const float* hs_rd, const float* ws_rd)
{
    auto load = [&](int buf, int c) {
        const char* hp = (const char*)(hbase + (size_t)c * 2048) + gtid * 16;
        uint32_t hd = hdst + buf * 8192 + gtid * 16;
        cp16_(hd, hp); cp16_(hd + 2048, hp + 2048);
        cp16_(hd + 4096, hp + 4096); cp16_(hd + 6144, hp + 6144);
        const char* wp = (const char*)(wbase + (size_t)c * 1024) + gtid * 16;
        uint32_t wd2 = wdst + buf * 4096 + gtid * 16;
        cp16_(wd2, wp); cp16_(wd2 + 2048, wp + 2048);
    };
    load(0, 0); CPCOMMIT();
    load(1, 1); CPCOMMIT();
    CPWAIT1(); __syncthreads();

    for (int c = 0; c < nc; c++) {
        int buf = c & 1;
        const float* hC = hs_rd + buf * 2048 + wg * 16;
        const float* wC = ws_rd + buf * 1024 + lane;
#pragma unroll 8
        for (int kk = 0; kk < KCH; kk++) {
            ulonglong2 hA = *(const ulonglong2*)(hC + kk * 64);
            ulonglong2 hB = *(const ulonglong2*)(hC + kk * 64 + 4);
            ulonglong2 hCc = *(const ulonglong2*)(hC + kk * 64 + 8);
            ulonglong2 hD = *(const ulonglong2*)(hC + kk * 64 + 12);
            float wv = wC[kk * 32];
            ull wd; asm("mov.b64 %0, {%1, %1};" : "=l"(wd) : "f"(wv));
            acc[0] = ffma2_(hA.x, wd, acc[0]);
            acc[1] = ffma2_(hA.y, wd, acc[1]);
            acc[2] = ffma2_(hB.x, wd, acc[2]);
            acc[3] = ffma2_(hB.y, wd, acc[3]);
            acc[4] = ffma2_(hCc.x, wd, acc[4]);
            acc[5] = ffma2_(hCc.y, wd, acc[5]);
            acc[6] = ffma2_(hD.x, wd, acc[6]);
            acc[7] = ffma2_(hD.y, wd, acc[7]);
        }
        __syncthreads();
        if (c + 2 < nc) load(buf, c + 2);
        CPCOMMIT(); CPWAIT1(); __syncthreads();
    }
}

// ---------------------------------------------------------------------------
// k_rnn: 512-step recurrence, one persistent kernel, 128 blocks x 256 thr.
// Block owns 8 units (32 z-cols). Split-K: warps 0-3 = K-half 0 (grp 0),
// warps 4-7 = K-half 1 (grp 1). Warp covers 32 cols x 16 rows (8 FFMA2 accs).
// Halves reduced through smem (aliased over the w buffers); grp 0 runs the
// epilogue: two 4x4 butterflies -> 4 rows x 4 gates per lane; c-state in regs.
// ---------------------------------------------------------------------------
__global__ __launch_bounds__(256, 1) void k_rnn(const float* __restrict__ b1) {
    __shared__ __align__(16) unsigned char sraw[49152];
    float* hs0 = (float*)sraw;                   // [grp][buf][32][64]  32KB
    float* ws0 = (float*)(sraw + 32768);         // [grp][buf][32][32]  16KB
    ull*   zred = (ull*)(sraw + 32768);          // alias, 8KB, used post-loop

    int tid = threadIdx.x;
    int grp = tid >> 7, gtid = tid & 127;
    int wg = gtid >> 5, lane = tid & 31;
    int u = lane & 7, g = lane >> 3;
    int bid = blockIdx.x, j = bid * 8 + u;
    int R = wg * 16 + g * 4;                     // epilogue base row (grp 0)

    uint32_t sbase = (uint32_t)__cvta_generic_to_shared(sraw);
    uint32_t hdst = sbase + grp * 16384;
    uint32_t wdst = sbase + 32768 + grp * 8192;
    const float* hs_rd = hs0 + grp * 4096;
    const float* ws_rd = ws0 + grp * 2048;

    const float* wAg = g_WA + (size_t)bid * 1024 * 32 + (grp ? 512 * 32 : 0);
    const float* wBg = g_WB + (size_t)bid * 2048 * 32 + (grp ? 1024 * 32 : 0);

    float b1v[4];
#pragma unroll
    for (int m = 0; m < 4; m++) b1v[m] = b1[m * NH + j];
    float c0[4] = {0.f, 0.f, 0.f, 0.f};
    float c1[4] = {0.f, 0.f, 0.f, 0.f};

    for (int t = 0; t < NT; t++) {
        int par = t & 1;
        const float* h0r = g_h0T + (size_t)par * SH;
        float*       h0w = g_h0T + (size_t)(par ^ 1) * SH;
        const float* h1r = g_h1T + (size_t)par * SH;
        float*       h1w = g_h1T + (size_t)(par ^ 1) * SH;

        // P0 prefetch for epilogue (grp 0 lanes only)
        float p[4][4];
        if (grp == 0) {
            size_t pb = ((size_t)t * NB + R) * NZ + j;
#pragma unroll
            for (int r = 0; r < 4; r++)
#pragma unroll
                for (int m = 0; m < 4; m++)
                    p[r][m] = g_P0[pb + (size_t)r * NZ + m * NH];
        }

        // ===== phase A: z0 = P0[t] + h0 @ U0 (K=1024, split 512/512) =====
        {
            ull acc[8] = {0ull,0ull,0ull,0ull,0ull,0ull,0ull,0ull};
            const float* hb = h0r + (grp ? 512 * 64 : 0);
            chunk_loop_(acc, hb, wAg, 16, hdst, wdst, gtid, wg, lane, hs_rd, ws_rd);
            if (grp == 1) {
#pragma unroll
                for (int s = 0; s < 8; s++) zred[(wg * 8 + s) * 32 + lane] = acc[s];
            }
            __syncthreads();
            if (grp == 0) {
#pragma unroll
                for (int s = 0; s < 8; s++) acc[s] = addf2_(acc[s], zred[(wg * 8 + s) * 32 + lane]);
                ull aE[4] = {acc[0], acc[2], acc[4], acc[6]};
                ull aO[4] = {acc[1], acc[3], acc[5], acc[7]};
                transpose4_(aE, g);
                transpose4_(aO, g);
                float zg[4][4];
#pragma unroll
                for (int m = 0; m < 4; m++) {
                    float2 e = unpack2_(aE[m]), o = unpack2_(aO[m]);
                    zg[m][0] = e.x; zg[m][1] = e.y; zg[m][2] = o.x; zg[m][3] = o.y;
                }
                float hv[4];
#pragma unroll
                for (int r = 0; r < 4; r++) {
                    float ig = sigmoidf_(zg[0][r] + p[r][0]);
                    float fg = sigmoidf_(zg[1][r] + p[r][1]);
                    float gg = tanhf(zg[2][r] + p[r][2]);
                    float og = sigmoidf_(zg[3][r] + p[r][3]);
                    c0[r] = fg * c0[r] + ig * gg;
                    hv[r] = og * tanhf(c0[r]);
                }
                *(float4*)&h0w[j * 64 + R] = make_float4(hv[0], hv[1], hv[2], hv[3]);
            }
        }
        grid_sync_();

        // ===== phase B: z1 = h0_new @ W1 + h1 @ U1 + b1 (K=2048, split 1024/1024)
        {
            ull acc[8] = {0ull,0ull,0ull,0ull,0ull,0ull,0ull,0ull};
            const float* hb = grp ? h1r : h0w;
            chunk_loop_(acc, hb, wBg, 32, hdst, wdst, gtid, wg, lane, hs_rd, ws_rd);
            if (grp == 1) {
#pragma unroll
                for (int s = 0; s < 8; s++) zred[(wg * 8 + s) * 32 + lane] = acc[s];
            }
            __syncthreads();
            if (grp == 0) {
#pragma unroll
                for (int s = 0; s < 8; s++) acc[s] = addf2_(acc[s], zred[(wg * 8 + s) * 32 + lane]);
                ull aE[4] = {acc[0], acc[2], acc[4], acc[6]};
                ull aO[4] = {acc[1], acc[3], acc[5], acc[7]};
                transpose4_(aE, g);
                transpose4_(aO, g);
                float zg[4][4];
#pragma unroll
                for (int m = 0; m < 4; m++) {
                    float2 e = unpack2_(aE[m]), o = unpack2_(aO[m]);
                    zg[m][0] = e.x; zg[m][1] = e.y; zg[m][2] = o.x; zg[m][3] = o.y;
                }
                float hv[4];
#pragma unroll
                for (int r = 0; r < 4; r++) {
                    float ig = sigmoidf_(zg[0][r] + b1v[0]);
                    float fg = sigmoidf_(zg[1][r] + b1v[1]);
                    float gg = tanhf(zg[2][r] + b1v[2]);
                    float og = sigmoidf_(zg[3][r] + b1v[3]);
                    c1[r] = fg * c1[r] + ig * gg;
                    hv[r] = og * tanhf(c1[r]);
                }
                *(float4*)&h1w[j * 64 + R] = make_float4(hv[0], hv[1], hv[2], hv[3]);
            }
        }
        grid_sync_();
    }
}

// ---------------------------------------------------------------------------
// k_out: out = tanh( h1_final @ Wo + bo ),  h1 stored transposed hT[k][b]
// ---------------------------------------------------------------------------
__global__ void k_out(const float* __restrict__ Wo, const float* __restrict__ bo,
                      float* __restrict__ out) {
    int idx = blockIdx.x * blockDim.x + threadIdx.x;
    if (idx >= NB * NDOUT) return;
    int n = idx & 127, b = idx >> 7;
    const float* hT = g_h1T;   // final h1 at parity 0 after T=512 steps
    float s0 = 0.f, s1 = 0.f, s2 = 0.f, s3 = 0.f;
#pragma unroll 4
    for (int k = 0; k < NH; k += 4) {
        s0 += hT[(k + 0) * 64 + b] * Wo[(size_t)(k + 0) * NDOUT + n];
        s1 += hT[(k + 1) * 64 + b] * Wo[(size_t)(k + 1) * NDOUT + n];
        s2 += hT[(k + 2) * 64 + b] * Wo[(size_t)(k + 2) * NDOUT + n];
        s3 += hT[(k + 3) * 64 + b] * Wo[(size_t)(k + 3) * NDOUT + n];
    }
    out[idx] = tanhf((s0 + s1) + (s2 + s3) + bo[n]);
}

// ---------------------------------------------------------------------------
extern "C" void kernel_launch(void* const* d_in, const int* in_sizes, int n_in,
                              void* d_out, int out_size) {
    const float* x  = (const float*)d_in[0];
    const float* Wi = (const float*)d_in[1];
    const float* bi = (const float*)d_in[2];
    const float* W0 = (const float*)d_in[3];
    const float* U0 = (const float*)d_in[4];
    const float* b0 = (const float*)d_in[5];
    const float* W1 = (const float*)d_in[6];
    const float* U1 = (const float*)d_in[7];
    const float* b1 = (const float*)d_in[8];
    const float* Wo = (const float*)d_in[9];
    const float* bo = (const float*)d_in[10];
    float* out = (float*)d_out;
    (void)in_sizes; (void)n_in; (void)out_size;

    k_init<<<512, 256>>>();
    k_prep<<<32768, 256>>>(U0, W1, U1);
    k_xin<<<dim3(16, 512), 256>>>(x, Wi, bi);
    k_p0<<<dim3(64, 256), 256>>>(W0, b0);
    k_rnn<<<NBLK, 256>>>(b1);
    k_out<<<32, 256>>>(Wo, bo, out);
}

// round 10
// speedup vs baseline: 2.4763x; 1.1591x over previous
#include <cuda_runtime.h>
#include <stdint.h>
#include <math.h>

#define NB 64
#define NT 512
#define NF 512
#define NDIN 1024
#define NH 1024
#define NZ 4096
#define NDOUT 128
#define SH (NB*NH)     // 65536 floats per h buffer
#define NBLK 128       // persistent blocks (1/SM, all co-resident)
#define KCH 32         // k per chunk in k_rnn
#define RNN_THREADS 512
#define RNN_SMEM (65536 + 32768)   // hs 64KB + ws 32KB

typedef unsigned long long ull;

// Scratch (device globals; no dynamic allocation allowed)
__device__ float g_xin[(size_t)NT * NB * NDIN];   // tanh(x@Wi+bi), rows r = t*NB+b
__device__ float g_P0[(size_t)NT * NB * NZ];      // xin@W0 + b0
__device__ float g_h0T[2 * SH];                   // transposed h0: [par][j][64 rows]
__device__ float g_h1T[2 * SH];                   // transposed h1
// packed recurrent weights (NOT duplicated), block-major:
// g_WA[bid*1024*32 + k*32 + lane] = U0[k][g*NH + bid*8+u], lane = g*8+u
__device__ float g_WA[(size_t)NBLK * 1024 * 32];    // 16 MB
// g_WB: k<1024 -> W1[k], k>=1024 -> U1[k-1024], same per-k lane packing
__device__ float g_WB[(size_t)NBLK * 2048 * 32];    // 32 MB

// grid barrier state
__device__ unsigned g_count;
__device__ volatile unsigned g_gen;

// ---------------------------------------------------------------------------
// packed f32x2 helpers (sm_103a dual-fp32 pipe, PTX-only)
// ---------------------------------------------------------------------------
__device__ __forceinline__ ull ffma2_(ull a, ull b, ull c) {
    ull d;
    asm("fma.rn.f32x2 %0, %1, %2, %3;" : "=l"(d) : "l"(a), "l"(b), "l"(c));
    return d;
}
__device__ __forceinline__ ull addf2_(ull a, ull b) {
    ull d;
    asm("add.rn.f32x2 %0, %1, %2;" : "=l"(d) : "l"(a), "l"(b));
    return d;
}
__device__ __forceinline__ float2 unpack2_(ull v) {
    float2 r;
    asm("mov.b64 {%0, %1}, %2;" : "=f"(r.x), "=f"(r.y) : "l"(v));
    return r;
}
__device__ __forceinline__ ull dup2_(float f) {
    ull d;
    asm("mov.b64 %0, {%1, %1};" : "=l"(d) : "f"(f));
    return d;
}

// cp.async, L2-only (.cg) — bypasses L1 so cross-SM h updates are never stale
__device__ __forceinline__ void cp16_(uint32_t dst, const void* src) {
    asm volatile("cp.async.cg.shared.global [%0], [%1], 16;" :: "r"(dst), "l"(src));
}
#define CPCOMMIT() asm volatile("cp.async.commit_group;" ::: "memory")
#define CPWAIT1()  asm volatile("cp.async.wait_group 1;"  ::: "memory")

__device__ __forceinline__ float sigmoidf_(float v) {
    return 1.f / (1.f + __expf(-v));
}

// ---------------------------------------------------------------------------
__global__ void k_init() {
    int idx = blockIdx.x * blockDim.x + threadIdx.x;
    if (idx < 2 * SH) { g_h0T[idx] = 0.f; g_h1T[idx] = 0.f; }
    if (idx == 0) { g_count = 0; g_gen = 0; }
}

// ---------------------------------------------------------------------------
// k_prep: pack recurrent weights into block-major lane streams.
// ---------------------------------------------------------------------------
__global__ void k_prep(const float* __restrict__ U0, const float* __restrict__ W1,
                       const float* __restrict__ U1) {
    int idx = blockIdx.x * blockDim.x + threadIdx.x;
    const int NWA = NBLK * 1024 * 32;      // 4M
    const int NWB = NBLK * 2048 * 32;      // 8M
    if (idx < NWA) {
        int l = idx & 31, k = (idx >> 5) & 1023, b = idx >> 15;
        int u = l & 7, g = l >> 3;
        g_WA[idx] = U0[(size_t)k * NZ + g * NH + b * 8 + u];
    }
    if (idx < NWB) {
        int l = idx & 31, k = (idx >> 5) & 2047, b = idx >> 16;
        int u = l & 7, g = l >> 3;
        g_WB[idx] = (k < 1024) ? W1[(size_t)k * NZ + g * NH + b * 8 + u]
                               : U1[(size_t)(k - 1024) * NZ + g * NH + b * 8 + u];
    }
}

// ---------------------------------------------------------------------------
// k_xin: xin[r, n] = tanh( x[b,t,:] @ Wi[:,n] + bi[n] ),  r = t*NB + b
// ---------------------------------------------------------------------------
__global__ __launch_bounds__(256) void k_xin(const float* __restrict__ x,
                                             const float* __restrict__ Wi,
                                             const float* __restrict__ bi) {
    __shared__ float As[16][64];
    __shared__ float Bs[16][64];
    int tid = threadIdx.x;
    int tx = tid & 15, ty = tid >> 4;
    int n0 = blockIdx.x * 64;
    int row0 = blockIdx.y * 64;

    float acc[4][4] = {};

    int ar = tid & 63, akq = tid >> 6;
    int R = row0 + ar;
    int bb = R & 63, tt = R >> 6;               // r = t*NB + b
    const float* aptr = x + ((size_t)bb * NT + tt) * NF + akq * 4;
    int bkk = tid >> 4, bnq = tid & 15;
    const float* bptr = Wi + (size_t)bkk * NDIN + n0 + bnq * 4;

    float4 pa = *(const float4*)aptr;
    float4 pb = *(const float4*)bptr;

    const int NC = NF / 16;
    for (int c = 0; c < NC; c++) {
        As[akq * 4 + 0][ar] = pa.x; As[akq * 4 + 1][ar] = pa.y;
        As[akq * 4 + 2][ar] = pa.z; As[akq * 4 + 3][ar] = pa.w;
        *(float4*)&Bs[bkk][bnq * 4] = pb;
        __syncthreads();
        if (c + 1 < NC) {
            pa = *(const float4*)(aptr + (c + 1) * 16);
            pb = *(const float4*)(bptr + (size_t)(c + 1) * 16 * NDIN);
        }
#pragma unroll
        for (int kk = 0; kk < 16; kk++) {
            float4 a = *(const float4*)&As[kk][ty * 4];
            float4 b = *(const float4*)&Bs[kk][tx * 4];
            acc[0][0] += a.x * b.x; acc[0][1] += a.x * b.y; acc[0][2] += a.x * b.z; acc[0][3] += a.x * b.w;
            acc[1][0] += a.y * b.x; acc[1][1] += a.y * b.y; acc[1][2] += a.y * b.z; acc[1][3] += a.y * b.w;
            acc[2][0] += a.z * b.x; acc[2][1] += a.z * b.y; acc[2][2] += a.z * b.z; acc[2][3] += a.z * b.w;
            acc[3][0] += a.w * b.x; acc[3][1] += a.w * b.y; acc[3][2] += a.w * b.z; acc[3][3] += a.w * b.w;
        }
        __syncthreads();
    }
#pragma unroll
    for (int i = 0; i < 4; i++) {
        int r = row0 + ty * 4 + i;
#pragma unroll
        for (int jx = 0; jx < 4; jx++) {
            int n = n0 + tx * 4 + jx;
            g_xin[(size_t)r * NDIN + n] = tanhf(acc[i][jx] + bi[n]);
        }
    }
}

// ---------------------------------------------------------------------------
// k_p0 v3: P0 = xin @ W0 + b0. FFMA2 with register-duplicated A rows and
// natural f32x2 column pairs from plain Bs — same smem traffic as scalar
// (3x LDS.128/kk), half the fma-pipe cycles.
// ---------------------------------------------------------------------------
__global__ __launch_bounds__(256) void k_p0(const float* __restrict__ W0,
                                            const float* __restrict__ b0) {
    __shared__ float As[16][128];
    __shared__ float Bs[16][64];
    int tid = threadIdx.x;
    int tx = tid & 15, ty = tid >> 4;
    int n0 = blockIdx.x * 64;
    int row0 = blockIdx.y * 128;

    ull acc[8][2] = {};              // [row][colpair]

    int ar = tid & 127, akq0 = tid >> 7;
    const float* aptr0 = g_xin + (size_t)(row0 + ar) * NDIN + akq0 * 4;
    const float* aptr1 = g_xin + (size_t)(row0 + ar) * NDIN + (akq0 + 2) * 4;
    int bkk = tid >> 4, bnq = tid & 15;
    const float* bptr = W0 + (size_t)bkk * NZ + n0 + bnq * 4;

    float4 pa0 = *(const float4*)aptr0;
    float4 pa1 = *(const float4*)aptr1;
    float4 pb  = *(const float4*)bptr;

    const int NC = NDIN / 16;
    for (int c = 0; c < NC; c++) {
        As[akq0 * 4 + 0][ar] = pa0.x; As[akq0 * 4 + 1][ar] = pa0.y;
        As[akq0 * 4 + 2][ar] = pa0.z; As[akq0 * 4 + 3][ar] = pa0.w;
        As[(akq0 + 2) * 4 + 0][ar] = pa1.x; As[(akq0 + 2) * 4 + 1][ar] = pa1.y;
        As[(akq0 + 2) * 4 + 2][ar] = pa1.z; As[(akq0 + 2) * 4 + 3][ar] = pa1.w;
        *(float4*)&Bs[bkk][bnq * 4] = pb;
        __syncthreads();
        if (c + 1 < NC) {
            pa0 = *(const float4*)(aptr0 + (c + 1) * 16);
            pa1 = *(const float4*)(aptr1 + (c + 1) * 16);
            pb  = *(const float4*)(bptr + (size_t)(c + 1) * 16 * NZ);
        }
#pragma unroll
        for (int kk = 0; kk < 16; kk++) {
            float4 a0 = *(const float4*)&As[kk][ty * 8];
            float4 a1 = *(const float4*)&As[kk][ty * 8 + 4];
            ulonglong2 b = *(const ulonglong2*)&Bs[kk][tx * 4];  // {b0,b1},{b2,b3}
            ull d;
            d = dup2_(a0.x); acc[0][0] = ffma2_(d, b.x, acc[0][0]); acc[0][1] = ffma2_(d, b.y, acc[0][1]);
            d = dup2_(a0.y); acc[1][0] = ffma2_(d, b.x, acc[1][0]); acc[1][1] = ffma2_(d, b.y, acc[1][1]);
            d = dup2_(a0.z); acc[2][0] = ffma2_(d, b.x, acc[2][0]); acc[2][1] = ffma2_(d, b.y, acc[2][1]);
            d = dup2_(a0.w); acc[3][0] = ffma2_(d, b.x, acc[3][0]); acc[3][1] = ffma2_(d, b.y, acc[3][1]);
            d = dup2_(a1.x); acc[4][0] = ffma2_(d, b.x, acc[4][0]); acc[4][1] = ffma2_(d, b.y, acc[4][1]);
            d = dup2_(a1.y); acc[5][0] = ffma2_(d, b.x, acc[5][0]); acc[5][1] = ffma2_(d, b.y, acc[5][1]);
            d = dup2_(a1.z); acc[6][0] = ffma2_(d, b.x, acc[6][0]); acc[6][1] = ffma2_(d, b.y, acc[6][1]);
            d = dup2_(a1.w); acc[7][0] = ffma2_(d, b.x, acc[7][0]); acc[7][1] = ffma2_(d, b.y, acc[7][1]);
        }
        __syncthreads();
    }
#pragma unroll
    for (int i = 0; i < 8; i++) {
        int r = row0 + ty * 8 + i;
        int n = n0 + tx * 4;
        float2 vA = unpack2_(acc[i][0]);
        float2 vB = unpack2_(acc[i][1]);
        g_P0[(size_t)r * NZ + n + 0] = vA.x + b0[n + 0];
        g_P0[(size_t)r * NZ + n + 1] = vA.y + b0[n + 1];
        g_P0[(size_t)r * NZ + n + 2] = vB.x + b0[n + 2];
        g_P0[(size_t)r * NZ + n + 3] = vB.y + b0[n + 3];
    }
}

// ---------------------------------------------------------------------------
// software grid barrier (all NBLK blocks co-resident)
// ---------------------------------------------------------------------------
__device__ __forceinline__ void grid_sync_() {
    __syncthreads();
    if (threadIdx.x == 0) {
        __threadfence();
        unsigned gen = g_gen;
        if (atomicAdd(&g_count, 1u) == NBLK - 1) {
            g_count = 0;
            __threadfence();
            g_gen = gen + 1;
        } else {
            while (g_gen == gen) { }
        }
        __threadfence();
    }
    __syncthreads();
}

// ---------------------------------------------------------------------------
// 4x4 transpose among lanes {u, u+8, u+16, u+24} (bits 3,4 of lane).
// ---------------------------------------------------------------------------
__device__ __forceinline__ void transpose4_(ull acc[4], int g) {
    ull x0 = (g & 1) ? acc[0] : acc[1];
    ull x1 = (g & 1) ? acc[2] : acc[3];
    x0 = __shfl_xor_sync(0xffffffffu, x0, 8);
    x1 = __shfl_xor_sync(0xffffffffu, x1, 8);
    if (g & 1) { acc[0] = x0; acc[2] = x1; } else { acc[1] = x0; acc[3] = x1; }
    x0 = (g & 2) ? acc[0] : acc[2];
    x1 = (g & 2) ? acc[1] : acc[3];
    x0 = __shfl_xor_sync(0xffffffffu, x0, 16);
    x1 = __shfl_xor_sync(0xffffffffu, x1, 16);
    if (g & 2) { acc[0] = x0; acc[1] = x1; } else { acc[2] = x0; acc[3] = x1; }
}

// ---------------------------------------------------------------------------
// chunk loop: acc[s] += sum_k {hT[k][2s],hT[k][2s+1]} * {w,w}
// 16 rows per warp; weights non-dup float, duplicated in-register.
// All 4 K-split groups run this with identical nc (sync counts match).
// ---------------------------------------------------------------------------
__device__ __forceinline__ void chunk_loop_(
    ull acc[8], const float* hbase, const float* wbase, int nc,
    uint32_t hdst, uint32_t wdst, int gtid, int wg, int lane,
    const float* hs_rd, const float* ws_rd)
{
    auto load = [&](int buf, int c) {
        const char* hp = (const char*)(hbase + (size_t)c * 2048) + gtid * 16;
        uint32_t hd = hdst + buf * 8192 + gtid * 16;
        cp16_(hd, hp); cp16_(hd + 2048, hp + 2048);
        cp16_(hd + 4096, hp + 4096); cp16_(hd + 6144, hp + 6144);
        const char* wp = (const char*)(wbase + (size_t)c * 1024) + gtid * 16;
        uint32_t wd2 = wdst + buf * 4096 + gtid * 16;
        cp16_(wd2, wp); cp16_(wd2 + 2048, wp + 2048);
    };
    load(0, 0); CPCOMMIT();
    load(1, 1); CPCOMMIT();
    CPWAIT1(); __syncthreads();

    for (int c = 0; c < nc; c++) {
        int buf = c & 1;
        const float* hC = hs_rd + buf * 2048 + wg * 16;
        const float* wC = ws_rd + buf * 1024 + lane;
#pragma unroll 8
        for (int kk = 0; kk < KCH; kk++) {
            ulonglong2 hA = *(const ulonglong2*)(hC + kk * 64);
            ulonglong2 hB = *(const ulonglong2*)(hC + kk * 64 + 4);
            ulonglong2 hCc = *(const ulonglong2*)(hC + kk * 64 + 8);
            ulonglong2 hD = *(const ulonglong2*)(hC + kk * 64 + 12);
            float wv = wC[kk * 32];
            ull wd; asm("mov.b64 %0, {%1, %1};" : "=l"(wd) : "f"(wv));
            acc[0] = ffma2_(hA.x, wd, acc[0]);
            acc[1] = ffma2_(hA.y, wd, acc[1]);
            acc[2] = ffma2_(hB.x, wd, acc[2]);
            acc[3] = ffma2_(hB.y, wd, acc[3]);
            acc[4] = ffma2_(hCc.x, wd, acc[4]);
            acc[5] = ffma2_(hCc.y, wd, acc[5]);
            acc[6] = ffma2_(hD.x, wd, acc[6]);
            acc[7] = ffma2_(hD.y, wd, acc[7]);
        }
        __syncthreads();
        if (c + 2 < nc) load(buf, c + 2);
        CPCOMMIT(); CPWAIT1(); __syncthreads();
    }
}

// ---------------------------------------------------------------------------
// k_rnn v3: 512-step recurrence, 128 blocks x 512 threads (16 warps/SM).
// Block owns 8 units (32 z-cols). 4-way split-K: grp = tid>>7 owns K-quarter
// grp. Warp covers 32 cols x 16 rows (8 FFMA2 accs/lane). Partials from
// grps 1-3 reduced into grp 0 via smem (aliased over hs); grp 0 runs the
// epilogue (two 4x4 butterflies -> 4 rows x 4 gates/lane); c-state in regs.
// Dynamic smem: hs[4][2][32][64] (64KB) + ws[4][2][32][32] (32KB).
// ---------------------------------------------------------------------------
__global__ __launch_bounds__(RNN_THREADS, 1) void k_rnn(const float* __restrict__ b1) {
    extern __shared__ __align__(16) unsigned char sraw[];
    float* hs0 = (float*)sraw;                   // 64KB
    float* ws0 = (float*)(sraw + 65536);         // 32KB
    ull*   zred = (ull*)sraw;                    // alias over hs (24KB used)

    int tid = threadIdx.x;
    int grp = tid >> 7, gtid = tid & 127;
    int wg = (gtid >> 5), lane = tid & 31;
    int u = lane & 7, g = lane >> 3;
    int bid = blockIdx.x, j = bid * 8 + u;
    int R = wg * 16 + g * 4;                     // epilogue base row (grp 0)

    uint32_t sbase = (uint32_t)__cvta_generic_to_shared(sraw);
    uint32_t hdst = sbase + grp * 16384;
    uint32_t wdst = sbase + 65536 + grp * 8192;
    const float* hs_rd = hs0 + grp * 4096;
    const float* ws_rd = ws0 + grp * 2048;

    const float* wAg = g_WA + (size_t)bid * 1024 * 32 + (size_t)grp * 256 * 32;
    const float* wBg = g_WB + (size_t)bid * 2048 * 32 + (size_t)grp * 512 * 32;

    float b1v[4];
#pragma unroll
    for (int m = 0; m < 4; m++) b1v[m] = b1[m * NH + j];
    float c0[4] = {0.f, 0.f, 0.f, 0.f};
    float c1[4] = {0.f, 0.f, 0.f, 0.f};

    for (int t = 0; t < NT; t++) {
        int par = t & 1;
        const float* h0r = g_h0T + (size_t)par * SH;
        float*       h0w = g_h0T + (size_t)(par ^ 1) * SH;
        const float* h1r = g_h1T + (size_t)par * SH;
        float*       h1w = g_h1T + (size_t)(par ^ 1) * SH;

        // P0 prefetch for epilogue (grp 0 lanes only)
        float p[4][4];
        if (grp == 0) {
            size_t pb = ((size_t)t * NB + R) * NZ + j;
#pragma unroll
            for (int r = 0; r < 4; r++)
#pragma unroll
                for (int m = 0; m < 4; m++)
                    p[r][m] = g_P0[pb + (size_t)r * NZ + m * NH];
        }

        // ===== phase A: z0 = P0[t] + h0 @ U0 (K=1024, 4x256 split) =====
        {
            ull acc[8] = {0ull,0ull,0ull,0ull,0ull,0ull,0ull,0ull};
            const float* hb = h0r + (size_t)grp * 256 * 64;
            chunk_loop_(acc, hb, wAg, 8, hdst, wdst, gtid, wg, lane, hs_rd, ws_rd);
            if (grp != 0) {
#pragma unroll
                for (int s = 0; s < 8; s++)
                    zred[((((grp - 1) * 4 + wg) * 8) + s) * 32 + lane] = acc[s];
            }
            __syncthreads();
            if (grp == 0) {
#pragma unroll
                for (int q = 0; q < 3; q++)
#pragma unroll
                    for (int s = 0; s < 8; s++)
                        acc[s] = addf2_(acc[s], zred[(((q * 4 + wg) * 8) + s) * 32 + lane]);
                ull aE[4] = {acc[0], acc[2], acc[4], acc[6]};
                ull aO[4] = {acc[1], acc[3], acc[5], acc[7]};
                transpose4_(aE, g);
                transpose4_(aO, g);
                float zg[4][4];
#pragma unroll
                for (int m = 0; m < 4; m++) {
                    float2 e = unpack2_(aE[m]), o = unpack2_(aO[m]);
                    zg[m][0] = e.x; zg[m][1] = e.y; zg[m][2] = o.x; zg[m][3] = o.y;
                }
                float hv[4];
#pragma unroll
                for (int r = 0; r < 4; r++) {
                    float ig = sigmoidf_(zg[0][r] + p[r][0]);
                    float fg = sigmoidf_(zg[1][r] + p[r][1]);
                    float gg = tanhf(zg[2][r] + p[r][2]);
                    float og = sigmoidf_(zg[3][r] + p[r][3]);
                    c0[r] = fg * c0[r] + ig * gg;
                    hv[r] = og * tanhf(c0[r]);
                }
                *(float4*)&h0w[j * 64 + R] = make_float4(hv[0], hv[1], hv[2], hv[3]);
            }
        }
        grid_sync_();

        // ===== phase B: z1 = h0_new @ W1 + h1 @ U1 + b1 (K=2048, 4x512 split)
        {
            ull acc[8] = {0ull,0ull,0ull,0ull,0ull,0ull,0ull,0ull};
            const float* hb = (grp < 2) ? (h0w + (size_t)grp * 512 * 64)
                                        : (h1r + (size_t)(grp - 2) * 512 * 64);
            chunk_loop_(acc, hb, wBg, 16, hdst, wdst, gtid, wg, lane, hs_rd, ws_rd);
            if (grp != 0) {
#pragma unroll
                for (int s = 0; s < 8; s++)
                    zred[((((grp - 1) * 4 + wg) * 8) + s) * 32 + lane] = acc[s];
            }
            __syncthreads();
            if (grp == 0) {
#pragma unroll
                for (int q = 0; q < 3; q++)
#pragma unroll
                    for (int s = 0; s < 8; s++)
                        acc[s] = addf2_(acc[s], zred[(((q * 4 + wg) * 8) + s) * 32 + lane]);
                ull aE[4] = {acc[0], acc[2], acc[4], acc[6]};
                ull aO[4] = {acc[1], acc[3], acc[5], acc[7]};
                transpose4_(aE, g);
                transpose4_(aO, g);
                float zg[4][4];
#pragma unroll
                for (int m = 0; m < 4; m++) {
                    float2 e = unpack2_(aE[m]), o = unpack2_(aO[m]);
                    zg[m][0] = e.x; zg[m][1] = e.y; zg[m][2] = o.x; zg[m][3] = o.y;
                }
                float hv[4];
#pragma unroll
                for (int r = 0; r < 4; r++) {
                    float ig = sigmoidf_(zg[0][r] + b1v[0]);
                    float fg = sigmoidf_(zg[1][r] + b1v[1]);
                    float gg = tanhf(zg[2][r] + b1v[2]);
                    float og = sigmoidf_(zg[3][r] + b1v[3]);
                    c1[r] = fg * c1[r] + ig * gg;
                    hv[r] = og * tanhf(c1[r]);
                }
                *(float4*)&h1w[j * 64 + R] = make_float4(hv[0], hv[1], hv[2], hv[3]);
            }
        }
        grid_sync_();
    }
}

// ---------------------------------------------------------------------------
// k_out: out = tanh( h1_final @ Wo + bo ),  h1 stored transposed hT[k][b]
// ---------------------------------------------------------------------------
__global__ void k_out(const float* __restrict__ Wo, const float* __restrict__ bo,
                      float* __restrict__ out) {
    int idx = blockIdx.x * blockDim.x + threadIdx.x;
    if (idx >= NB * NDOUT) return;
    int n = idx & 127, b = idx >> 7;
    const float* hT = g_h1T;   // final h1 at parity 0 after T=512 steps
    float s0 = 0.f, s1 = 0.f, s2 = 0.f, s3 = 0.f;
#pragma unroll 4
    for (int k = 0; k < NH; k += 4) {
        s0 += hT[(k + 0) * 64 + b] * Wo[(size_t)(k + 0) * NDOUT + n];
        s1 += hT[(k + 1) * 64 + b] * Wo[(size_t)(k + 1) * NDOUT + n];
        s2 += hT[(k + 2) * 64 + b] * Wo[(size_t)(k + 2) * NDOUT + n];
        s3 += hT[(k + 3) * 64 + b] * Wo[(size_t)(k + 3) * NDOUT + n];
    }
    out[idx] = tanhf((s0 + s1) + (s2 + s3) + bo[n]);
}

// ---------------------------------------------------------------------------
extern "C" void kernel_launch(void* const* d_in, const int* in_sizes, int n_in,
                              void* d_out, int out_size) {
    const float* x  = (const float*)d_in[0];
    const float* Wi = (const float*)d_in[1];
    const float* bi = (const float*)d_in[2];
    const float* W0 = (const float*)d_in[3];
    const float* U0 = (const float*)d_in[4];
    const float* b0 = (const float*)d_in[5];
    const float* W1 = (const float*)d_in[6];
    const float* U1 = (const float*)d_in[7];
    const float* b1 = (const float*)d_in[8];
    const float* Wo = (const float*)d_in[9];
    const float* bo = (const float*)d_in[10];
    float* out = (float*)d_out;
    (void)in_sizes; (void)n_in; (void)out_size;

    cudaFuncSetAttribute(k_rnn, cudaFuncAttributeMaxDynamicSharedMemorySize, RNN_SMEM);

    k_init<<<512, 256>>>();
    k_prep<<<32768, 256>>>(U0, W1, U1);
    k_xin<<<dim3(16, 512), 256>>>(x, Wi, bi);
    k_p0<<<dim3(64, 256), 256>>>(W0, b0);
    k_rnn<<<NBLK, RNN_THREADS, RNN_SMEM>>>(b1);
    k_out<<<32, 256>>>(Wo, bo, out);
}

// round 11
// speedup vs baseline: 3.3433x; 1.3501x over previous
#include <cuda_runtime.h>
#include <stdint.h>
#include <math.h>

#define NB 64
#define NT 512
#define NF 512
#define NDIN 1024
#define NH 1024
#define NZ 4096
#define NDOUT 128
#define SH (NB*NH)     // 65536 floats per h buffer
#define NBLK 128       // persistent blocks (1/SM, all co-resident)
#define KCH 32         // k per chunk in k_rnn
#define RNN_THREADS 512
// smem: hs 64KB + ws 64KB + zred 48KB
#define RNN_SMEM (65536 + 65536 + 49152)

typedef unsigned long long ull;

// Scratch (device globals; no dynamic allocation allowed)
__device__ float g_xin[(size_t)NT * NB * NDIN];   // tanh(x@Wi+bi), rows r = t*NB+b
__device__ float g_P0[(size_t)NT * NB * NZ];      // xin@W0 + b0
__device__ float g_h0T[2 * SH];                   // transposed h0: [par][j][64 rows]
__device__ float g_h1T[2 * SH];                   // transposed h1
// Region-1 weights (h0-driven), per-lane float2 {U0, W1}:
// g_WC[(bid*1024 + k)*64 + lane*2 + {0,1}] = {U0,W1}[k][g*NH + bid*8+u]
__device__ float g_WC[(size_t)NBLK * 1024 * 64];    // 32 MB
// Region-2 weights (h1-driven): g_WD[(bid*1024 + k)*32 + lane] = U1[k][col]
__device__ float g_WD[(size_t)NBLK * 1024 * 32];    // 16 MB

// grid barrier state
__device__ unsigned g_count;
__device__ volatile unsigned g_gen;

// ---------------------------------------------------------------------------
// packed f32x2 helpers (sm_103a dual-fp32 pipe, PTX-only)
// ---------------------------------------------------------------------------
__device__ __forceinline__ ull ffma2_(ull a, ull b, ull c) {
    ull d;
    asm("fma.rn.f32x2 %0, %1, %2, %3;" : "=l"(d) : "l"(a), "l"(b), "l"(c));
    return d;
}
__device__ __forceinline__ ull addf2_(ull a, ull b) {
    ull d;
    asm("add.rn.f32x2 %0, %1, %2;" : "=l"(d) : "l"(a), "l"(b));
    return d;
}
__device__ __forceinline__ float2 unpack2_(ull v) {
    float2 r;
    asm("mov.b64 {%0, %1}, %2;" : "=f"(r.x), "=f"(r.y) : "l"(v));
    return r;
}
__device__ __forceinline__ ull dup2_(float f) {
    ull d;
    asm("mov.b64 %0, {%1, %1};" : "=l"(d) : "f"(f));
    return d;
}

// cp.async, L2-only (.cg) — bypasses L1 so cross-SM h updates are never stale
__device__ __forceinline__ void cp16_(uint32_t dst, const void* src) {
    asm volatile("cp.async.cg.shared.global [%0], [%1], 16;" :: "r"(dst), "l"(src));
}
#define CPCOMMIT() asm volatile("cp.async.commit_group;" ::: "memory")
#define CPWAIT1()  asm volatile("cp.async.wait_group 1;"  ::: "memory")

__device__ __forceinline__ float sigmoidf_(float v) {
    return 1.f / (1.f + __expf(-v));
}

// ---------------------------------------------------------------------------
__global__ void k_init() {
    int idx = blockIdx.x * blockDim.x + threadIdx.x;
    if (idx < 2 * SH) { g_h0T[idx] = 0.f; g_h1T[idx] = 0.f; }
    if (idx == 0) { g_count = 0; g_gen = 0; }
}

// ---------------------------------------------------------------------------
// k_prep: pack recurrent weights into block-major lane streams.
// ---------------------------------------------------------------------------
__global__ void k_prep(const float* __restrict__ U0, const float* __restrict__ W1,
                       const float* __restrict__ U1) {
    int idx = blockIdx.x * blockDim.x + threadIdx.x;
    const int NWC = NBLK * 1024 * 64;      // 8M
    const int NWD = NBLK * 1024 * 32;      // 4M
    if (idx < NWC) {
        int lane2 = idx & 63, k = (idx >> 6) & 1023, b = idx >> 16;
        int lane = lane2 >> 1, which = lane2 & 1;
        int col = (lane >> 3) * NH + b * 8 + (lane & 7);
        g_WC[idx] = which ? W1[(size_t)k * NZ + col] : U0[(size_t)k * NZ + col];
    }
    if (idx < NWD) {
        int lane = idx & 31, k = (idx >> 5) & 1023, b = idx >> 15;
        int col = (lane >> 3) * NH + b * 8 + (lane & 7);
        g_WD[idx] = U1[(size_t)k * NZ + col];
    }
}

// ---------------------------------------------------------------------------
// k_xin: xin[r, n] = tanh( x[b,t,:] @ Wi[:,n] + bi[n] ),  r = t*NB + b
// ---------------------------------------------------------------------------
__global__ __launch_bounds__(256) void k_xin(const float* __restrict__ x,
                                             const float* __restrict__ Wi,
                                             const float* __restrict__ bi) {
    __shared__ float As[16][64];
    __shared__ float Bs[16][64];
    int tid = threadIdx.x;
    int tx = tid & 15, ty = tid >> 4;
    int n0 = blockIdx.x * 64;
    int row0 = blockIdx.y * 64;

    float acc[4][4] = {};

    int ar = tid & 63, akq = tid >> 6;
    int R = row0 + ar;
    int bb = R & 63, tt = R >> 6;               // r = t*NB + b
    const float* aptr = x + ((size_t)bb * NT + tt) * NF + akq * 4;
    int bkk = tid >> 4, bnq = tid & 15;
    const float* bptr = Wi + (size_t)bkk * NDIN + n0 + bnq * 4;

    float4 pa = *(const float4*)aptr;
    float4 pb = *(const float4*)bptr;

    const int NC = NF / 16;
    for (int c = 0; c < NC; c++) {
        As[akq * 4 + 0][ar] = pa.x; As[akq * 4 + 1][ar] = pa.y;
        As[akq * 4 + 2][ar] = pa.z; As[akq * 4 + 3][ar] = pa.w;
        *(float4*)&Bs[bkk][bnq * 4] = pb;
        __syncthreads();
        if (c + 1 < NC) {
            pa = *(const float4*)(aptr + (c + 1) * 16);
            pb = *(const float4*)(bptr + (size_t)(c + 1) * 16 * NDIN);
        }
#pragma unroll
        for (int kk = 0; kk < 16; kk++) {
            float4 a = *(const float4*)&As[kk][ty * 4];
            float4 b = *(const float4*)&Bs[kk][tx * 4];
            acc[0][0] += a.x * b.x; acc[0][1] += a.x * b.y; acc[0][2] += a.x * b.z; acc[0][3] += a.x * b.w;
            acc[1][0] += a.y * b.x; acc[1][1] += a.y * b.y; acc[1][2] += a.y * b.z; acc[1][3] += a.y * b.w;
            acc[2][0] += a.z * b.x; acc[2][1] += a.z * b.y; acc[2][2] += a.z * b.z; acc[2][3] += a.z * b.w;
            acc[3][0] += a.w * b.x; acc[3][1] += a.w * b.y; acc[3][2] += a.w * b.z; acc[3][3] += a.w * b.w;
        }
        __syncthreads();
    }
#pragma unroll
    for (int i = 0; i < 4; i++) {
        int r = row0 + ty * 4 + i;
#pragma unroll
        for (int jx = 0; jx < 4; jx++) {
            int n = n0 + tx * 4 + jx;
            g_xin[(size_t)r * NDIN + n] = tanhf(acc[i][jx] + bi[n]);
        }
    }
}

// ---------------------------------------------------------------------------
// k_p0 v3: P0 = xin @ W0 + b0. FFMA2 with register-duplicated A rows and
// natural f32x2 column pairs from plain Bs.
// ---------------------------------------------------------------------------
__global__ __launch_bounds__(256) void k_p0(const float* __restrict__ W0,
                                            const float* __restrict__ b0) {
    __shared__ float As[16][128];
    __shared__ float Bs[16][64];
    int tid = threadIdx.x;
    int tx = tid & 15, ty = tid >> 4;
    int n0 = blockIdx.x * 64;
    int row0 = blockIdx.y * 128;

    ull acc[8][2] = {};              // [row][colpair]

    int ar = tid & 127, akq0 = tid >> 7;
    const float* aptr0 = g_xin + (size_t)(row0 + ar) * NDIN + akq0 * 4;
    const float* aptr1 = g_xin + (size_t)(row0 + ar) * NDIN + (akq0 + 2) * 4;
    int bkk = tid >> 4, bnq = tid & 15;
    const float* bptr = W0 + (size_t)bkk * NZ + n0 + bnq * 4;

    float4 pa0 = *(const float4*)aptr0;
    float4 pa1 = *(const float4*)aptr1;
    float4 pb  = *(const float4*)bptr;

    const int NC = NDIN / 16;
    for (int c = 0; c < NC; c++) {
        As[akq0 * 4 + 0][ar] = pa0.x; As[akq0 * 4 + 1][ar] = pa0.y;
        As[akq0 * 4 + 2][ar] = pa0.z; As[akq0 * 4 + 3][ar] = pa0.w;
        As[(akq0 + 2) * 4 + 0][ar] = pa1.x; As[(akq0 + 2) * 4 + 1][ar] = pa1.y;
        As[(akq0 + 2) * 4 + 2][ar] = pa1.z; As[(akq0 + 2) * 4 + 3][ar] = pa1.w;
        *(float4*)&Bs[bkk][bnq * 4] = pb;
        __syncthreads();
        if (c + 1 < NC) {
            pa0 = *(const float4*)(aptr0 + (c + 1) * 16);
            pa1 = *(const float4*)(aptr1 + (c + 1) * 16);
            pb  = *(const float4*)(bptr + (size_t)(c + 1) * 16 * NZ);
        }
#pragma unroll
        for (int kk = 0; kk < 16; kk++) {
            float4 a0 = *(const float4*)&As[kk][ty * 8];
            float4 a1 = *(const float4*)&As[kk][ty * 8 + 4];
            ulonglong2 b = *(const ulonglong2*)&Bs[kk][tx * 4];
            ull d;
            d = dup2_(a0.x); acc[0][0] = ffma2_(d, b.x, acc[0][0]); acc[0][1] = ffma2_(d, b.y, acc[0][1]);
            d = dup2_(a0.y); acc[1][0] = ffma2_(d, b.x, acc[1][0]); acc[1][1] = ffma2_(d, b.y, acc[1][1]);
            d = dup2_(a0.z); acc[2][0] = ffma2_(d, b.x, acc[2][0]); acc[2][1] = ffma2_(d, b.y, acc[2][1]);
            d = dup2_(a0.w); acc[3][0] = ffma2_(d, b.x, acc[3][0]); acc[3][1] = ffma2_(d, b.y, acc[3][1]);
            d = dup2_(a1.x); acc[4][0] = ffma2_(d, b.x, acc[4][0]); acc[4][1] = ffma2_(d, b.y, acc[4][1]);
            d = dup2_(a1.y); acc[5][0] = ffma2_(d, b.x, acc[5][0]); acc[5][1] = ffma2_(d, b.y, acc[5][1]);
            d = dup2_(a1.z); acc[6][0] = ffma2_(d, b.x, acc[6][0]); acc[6][1] = ffma2_(d, b.y, acc[6][1]);
            d = dup2_(a1.w); acc[7][0] = ffma2_(d, b.x, acc[7][0]); acc[7][1] = ffma2_(d, b.y, acc[7][1]);
        }
        __syncthreads();
    }
#pragma unroll
    for (int i = 0; i < 8; i++) {
        int r = row0 + ty * 8 + i;
        int n = n0 + tx * 4;
        float2 vA = unpack2_(acc[i][0]);
        float2 vB = unpack2_(acc[i][1]);
        g_P0[(size_t)r * NZ + n + 0] = vA.x + b0[n + 0];
        g_P0[(size_t)r * NZ + n + 1] = vA.y + b0[n + 1];
        g_P0[(size_t)r * NZ + n + 2] = vB.x + b0[n + 2];
        g_P0[(size_t)r * NZ + n + 3] = vB.y + b0[n + 3];
    }
}

// ---------------------------------------------------------------------------
// software grid barrier (all NBLK blocks co-resident)
// ---------------------------------------------------------------------------
__device__ __forceinline__ void grid_sync_() {
    __syncthreads();
    if (threadIdx.x == 0) {
        __threadfence();
        unsigned gen = g_gen;
        if (atomicAdd(&g_count, 1u) == NBLK - 1) {
            g_count = 0;
            __threadfence();
            g_gen = gen + 1;
        } else {
            while (g_gen == gen) { }
        }
        __threadfence();
    }
    __syncthreads();
}

// ---------------------------------------------------------------------------
// 4x4 transpose among lanes {u, u+8, u+16, u+24} (bits 3,4 of lane).
// ---------------------------------------------------------------------------
__device__ __forceinline__ void transpose4_(ull acc[4], int g) {
    ull x0 = (g & 1) ? acc[0] : acc[1];
    ull x1 = (g & 1) ? acc[2] : acc[3];
    x0 = __shfl_xor_sync(0xffffffffu, x0, 8);
    x1 = __shfl_xor_sync(0xffffffffu, x1, 8);
    if (g & 1) { acc[0] = x0; acc[2] = x1; } else { acc[1] = x0; acc[3] = x1; }
    x0 = (g & 2) ? acc[0] : acc[2];
    x1 = (g & 2) ? acc[1] : acc[3];
    x0 = __shfl_xor_sync(0xffffffffu, x0, 16);
    x1 = __shfl_xor_sync(0xffffffffu, x1, 16);
    if (g & 2) { acc[0] = x0; acc[1] = x1; } else { acc[2] = x0; acc[3] = x1; }
}

// ---------------------------------------------------------------------------
// k_rnn v4: merged-phase recurrence. Phase p computes z0(p) (layer-0 step p,
// producing h0(p+1), active p<512) AND z1(p-1) (layer-1 step p-1, producing
// h1(p), active p>0) in ONE 3072-K pass with ONE grid sync.
//   Region 1 (K=1024, h0(p)): each k feeds BOTH z0 (U0) and z1 (W1) — h
//     stream shared, weights packed {U0,W1} float2 per lane.
//   Region 2 (K=1024, h1(p-1)): z1 only (U1).
// 4-way split-K (grp = tid>>7, 256 k of each region per grp). Named barrier
// per grp in the chunk loop (no cross-grp coupling). Partials reduced into
// grp 0 via dedicated zred; grp 0 runs both epilogues. c-state in registers.
// ---------------------------------------------------------------------------
__global__ __launch_bounds__(RNN_THREADS, 1) void k_rnn(const float* __restrict__ b1) {
    extern __shared__ __align__(16) unsigned char sraw[];
    // hs [4][2][32][64] 64KB | ws [4][2][2048f] 64KB | zred 48KB
    ull* zred = (ull*)(sraw + 131072);

    int tid = threadIdx.x;
    int grp = tid >> 7, gtid = tid & 127;
    int wg = (gtid >> 5), lane = tid & 31;
    int u = lane & 7, g = lane >> 3;
    int bid = blockIdx.x, j = bid * 8 + u;
    int R = wg * 16 + g * 4;                     // epilogue base row (grp 0)

    uint32_t sbase = (uint32_t)__cvta_generic_to_shared(sraw);
    uint32_t hdst = sbase + grp * 16384;
    uint32_t wdst = sbase + 65536 + grp * 16384;
    const float* hs_rd = (const float*)sraw + grp * 4096;
    const float* ws_rd = (const float*)(sraw + 65536) + grp * 4096;

    const float* wcg = g_WC + (size_t)bid * 1024 * 64 + (size_t)grp * 256 * 64;
    const float* wdg = g_WD + (size_t)bid * 1024 * 32 + (size_t)grp * 256 * 32;

    float b1v[4];
#pragma unroll
    for (int m = 0; m < 4; m++) b1v[m] = b1[m * NH + j];
    float c0[4] = {0.f, 0.f, 0.f, 0.f};
    float c1[4] = {0.f, 0.f, 0.f, 0.f};

    for (int p = 0; p <= NT; p++) {
        int par = p & 1;
        const float* h0g = g_h0T + (size_t)par * SH + (size_t)grp * 256 * 64;
        const float* h1g = g_h1T + (size_t)(par ^ 1) * SH + (size_t)grp * 256 * 64;
        float* h0w = g_h0T + (size_t)(par ^ 1) * SH;   // h0(p+1)
        float* h1w = g_h1T + (size_t)par * SH;         // h1(p)

        // P0 prefetch for A epilogue (grp 0 only, p<512)
        float pz[4][4];
        if (grp == 0 && p < NT) {
            size_t pb = ((size_t)p * NB + R) * NZ + j;
#pragma unroll
            for (int r = 0; r < 4; r++)
#pragma unroll
                for (int m = 0; m < 4; m++)
                    pz[r][m] = g_P0[pb + (size_t)r * NZ + m * NH];
        }

        ull accA[8] = {0ull,0ull,0ull,0ull,0ull,0ull,0ull,0ull};
        ull accB[8] = {0ull,0ull,0ull,0ull,0ull,0ull,0ull,0ull};

        auto barg = [&] {
            asm volatile("bar.sync %0, %1;" :: "r"(grp + 1), "r"(128) : "memory");
        };
        auto load = [&](int buf, int c) {
            const char* hp;
            const char* wp;
            int nw;
            if (c < 8) {
                hp = (const char*)(h0g + c * 2048);
                wp = (const char*)(wcg + (size_t)c * 2048);
                nw = 4;
            } else {
                hp = (const char*)(h1g + (c - 8) * 2048);
                wp = (const char*)(wdg + (size_t)(c - 8) * 1024);
                nw = 2;
            }
            hp += gtid * 16;
            uint32_t hd = hdst + buf * 8192 + gtid * 16;
            cp16_(hd, hp); cp16_(hd + 2048, hp + 2048);
            cp16_(hd + 4096, hp + 4096); cp16_(hd + 6144, hp + 6144);
            wp += gtid * 16;
            uint32_t wd = wdst + buf * 8192 + gtid * 16;
            cp16_(wd, wp); cp16_(wd + 2048, wp + 2048);
            if (nw == 4) { cp16_(wd + 4096, wp + 4096); cp16_(wd + 6144, wp + 6144); }
        };

        load(0, 0); CPCOMMIT();
        load(1, 1); CPCOMMIT();
        CPWAIT1(); barg();

        for (int c = 0; c < 16; c++) {
            int buf = c & 1;
            const float* hC = hs_rd + buf * 2048 + wg * 16;
            if (c < 8) {
                const float2* wC = (const float2*)(ws_rd + buf * 2048);
#pragma unroll 8
                for (int kk = 0; kk < KCH; kk++) {
                    ulonglong2 hA = *(const ulonglong2*)(hC + kk * 64);
                    ulonglong2 hB = *(const ulonglong2*)(hC + kk * 64 + 4);
                    ulonglong2 hCc = *(const ulonglong2*)(hC + kk * 64 + 8);
                    ulonglong2 hD = *(const ulonglong2*)(hC + kk * 64 + 12);
                    float2 wv = wC[kk * 32 + lane];
                    ull d0 = dup2_(wv.x);
                    ull d1 = dup2_(wv.y);
                    accA[0] = ffma2_(hA.x, d0, accA[0]);
                    accA[1] = ffma2_(hA.y, d0, accA[1]);
                    accA[2] = ffma2_(hB.x, d0, accA[2]);
                    accA[3] = ffma2_(hB.y, d0, accA[3]);
                    accA[4] = ffma2_(hCc.x, d0, accA[4]);
                    accA[5] = ffma2_(hCc.y, d0, accA[5]);
                    accA[6] = ffma2_(hD.x, d0, accA[6]);
                    accA[7] = ffma2_(hD.y, d0, accA[7]);
                    accB[0] = ffma2_(hA.x, d1, accB[0]);
                    accB[1] = ffma2_(hA.y, d1, accB[1]);
                    accB[2] = ffma2_(hB.x, d1, accB[2]);
                    accB[3] = ffma2_(hB.y, d1, accB[3]);
                    accB[4] = ffma2_(hCc.x, d1, accB[4]);
                    accB[5] = ffma2_(hCc.y, d1, accB[5]);
                    accB[6] = ffma2_(hD.x, d1, accB[6]);
                    accB[7] = ffma2_(hD.y, d1, accB[7]);
                }
            } else {
                const float* wC = ws_rd + buf * 2048;
#pragma unroll 8
                for (int kk = 0; kk < KCH; kk++) {
                    ulonglong2 hA = *(const ulonglong2*)(hC + kk * 64);
                    ulonglong2 hB = *(const ulonglong2*)(hC + kk * 64 + 4);
                    ulonglong2 hCc = *(const ulonglong2*)(hC + kk * 64 + 8);
                    ulonglong2 hD = *(const ulonglong2*)(hC + kk * 64 + 12);
                    ull d1 = dup2_(wC[kk * 32 + lane]);
                    accB[0] = ffma2_(hA.x, d1, accB[0]);
                    accB[1] = ffma2_(hA.y, d1, accB[1]);
                    accB[2] = ffma2_(hB.x, d1, accB[2]);
                    accB[3] = ffma2_(hB.y, d1, accB[3]);
                    accB[4] = ffma2_(hCc.x, d1, accB[4]);
                    accB[5] = ffma2_(hCc.y, d1, accB[5]);
                    accB[6] = ffma2_(hD.x, d1, accB[6]);
                    accB[7] = ffma2_(hD.y, d1, accB[7]);
                }
            }
            barg();
            if (c + 2 < 16) load(buf, c + 2);
            CPCOMMIT(); CPWAIT1(); barg();
        }

        // ---- reduce partials into grp 0 ----
        if (grp != 0) {
            int base = ((grp - 1) * 4 + wg) * 16;
#pragma unroll
            for (int s = 0; s < 8; s++) {
                zred[(base + s) * 32 + lane] = accA[s];
                zred[(base + 8 + s) * 32 + lane] = accB[s];
            }
        }
        __syncthreads();
        if (grp == 0) {
#pragma unroll
            for (int q = 0; q < 3; q++) {
                int base = (q * 4 + wg) * 16;
#pragma unroll
                for (int s = 0; s < 8; s++) {
                    accA[s] = addf2_(accA[s], zred[(base + s) * 32 + lane]);
                    accB[s] = addf2_(accB[s], zred[(base + 8 + s) * 32 + lane]);
                }
            }
            // ---- A epilogue: h0(p+1) ----
            if (p < NT) {
                ull aE[4] = {accA[0], accA[2], accA[4], accA[6]};
                ull aO[4] = {accA[1], accA[3], accA[5], accA[7]};
                transpose4_(aE, g);
                transpose4_(aO, g);
                float zg[4][4];
#pragma unroll
                for (int m = 0; m < 4; m++) {
                    float2 e = unpack2_(aE[m]), o = unpack2_(aO[m]);
                    zg[m][0] = e.x; zg[m][1] = e.y; zg[m][2] = o.x; zg[m][3] = o.y;
                }
                float hv[4];
#pragma unroll
                for (int r = 0; r < 4; r++) {
                    float ig = sigmoidf_(zg[0][r] + pz[r][0]);
                    float fg = sigmoidf_(zg[1][r] + pz[r][1]);
                    float gg = tanhf(zg[2][r] + pz[r][2]);
                    float og = sigmoidf_(zg[3][r] + pz[r][3]);
                    c0[r] = fg * c0[r] + ig * gg;
                    hv[r] = og * tanhf(c0[r]);
                }
                *(float4*)&h0w[j * 64 + R] = make_float4(hv[0], hv[1], hv[2], hv[3]);
            }
            // ---- B epilogue: h1(p) ----
            if (p > 0) {
                ull aE[4] = {accB[0], accB[2], accB[4], accB[6]};
                ull aO[4] = {accB[1], accB[3], accB[5], accB[7]};
                transpose4_(aE, g);
                transpose4_(aO, g);
                float zg[4][4];
#pragma unroll
                for (int m = 0; m < 4; m++) {
                    float2 e = unpack2_(aE[m]), o = unpack2_(aO[m]);
                    zg[m][0] = e.x; zg[m][1] = e.y; zg[m][2] = o.x; zg[m][3] = o.y;
                }
                float hv[4];
#pragma unroll
                for (int r = 0; r < 4; r++) {
                    float ig = sigmoidf_(zg[0][r] + b1v[0]);
                    float fg = sigmoidf_(zg[1][r] + b1v[1]);
                    float gg = tanhf(zg[2][r] + b1v[2]);
                    float og = sigmoidf_(zg[3][r] + b1v[3]);
                    c1[r] = fg * c1[r] + ig * gg;
                    hv[r] = og * tanhf(c1[r]);
                }
                *(float4*)&h1w[j * 64 + R] = make_float4(hv[0], hv[1], hv[2], hv[3]);
            }
        }
        grid_sync_();
    }
}

// ---------------------------------------------------------------------------
// k_out: out = tanh( h1_final @ Wo + bo ),  h1 stored transposed hT[k][b]
// ---------------------------------------------------------------------------
__global__ void k_out(const float* __restrict__ Wo, const float* __restrict__ bo,
                      float* __restrict__ out) {
    int idx = blockIdx.x * blockDim.x + threadIdx.x;
    if (idx >= NB * NDOUT) return;
    int n = idx & 127, b = idx >> 7;
    const float* hT = g_h1T;   // h1(512) at parity 0
    float s0 = 0.f, s1 = 0.f, s2 = 0.f, s3 = 0.f;
#pragma unroll 4
    for (int k = 0; k < NH; k += 4) {
        s0 += hT[(k + 0) * 64 + b] * Wo[(size_t)(k + 0) * NDOUT + n];
        s1 += hT[(k + 1) * 64 + b] * Wo[(size_t)(k + 1) * NDOUT + n];
        s2 += hT[(k + 2) * 64 + b] * Wo[(size_t)(k + 2) * NDOUT + n];
        s3 += hT[(k + 3) * 64 + b] * Wo[(size_t)(k + 3) * NDOUT + n];
    }
    out[idx] = tanhf((s0 + s1) + (s2 + s3) + bo[n]);
}

// ---------------------------------------------------------------------------
extern "C" void kernel_launch(void* const* d_in, const int* in_sizes, int n_in,
                              void* d_out, int out_size) {
    const float* x  = (const float*)d_in[0];
    const float* Wi = (const float*)d_in[1];
    const float* bi = (const float*)d_in[2];
    const float* W0 = (const float*)d_in[3];
    const float* U0 = (const float*)d_in[4];
    const float* b0 = (const float*)d_in[5];
    const float* W1 = (const float*)d_in[6];
    const float* U1 = (const float*)d_in[7];
    const float* b1 = (const float*)d_in[8];
    const float* Wo = (const float*)d_in[9];
    const float* bo = (const float*)d_in[10];
    float* out = (float*)d_out;
    (void)in_sizes; (void)n_in; (void)out_size;

    cudaFuncSetAttribute(k_rnn, cudaFuncAttributeMaxDynamicSharedMemorySize, RNN_SMEM);

    k_init<<<512, 256>>>();
    k_prep<<<32768, 256>>>(U0, W1, U1);
    k_xin<<<dim3(16, 512), 256>>>(x, Wi, bi);
    k_p0<<<dim3(64, 256), 256>>>(W0, b0);
    k_rnn<<<NBLK, RNN_THREADS, RNN_SMEM>>>(b1);
    k_out<<<32, 256>>>(Wo, bo, out);
}

// round 12
// speedup vs baseline: 3.3814x; 1.0114x over previous
#include <cuda_runtime.h>
#include <stdint.h>
#include <math.h>

#define NB 64
#define NT 512
#define NF 512
#define NDIN 1024
#define NH 1024
#define NZ 4096
#define NDOUT 128
#define SH (NB*NH)     // 65536 floats per h buffer
#define NBLK 128       // persistent blocks (1/SM, all co-resident)
#define KCH 32         // k per chunk in k_rnn
#define RNN_THREADS 512
// smem: hs 64KB + ws 64KB + zred 48KB
#define RNN_SMEM (65536 + 65536 + 49152)

typedef unsigned long long ull;

// Scratch (device globals; no dynamic allocation allowed)
__device__ float g_xin[(size_t)NT * NB * NDIN];   // tanh(x@Wi+bi), rows r = t*NB+b
__device__ float g_P0[(size_t)NT * NB * NZ];      // xin@W0 + b0
__device__ float g_h0T[2 * SH];                   // transposed h0: [par][j][64 rows]
__device__ float g_h1T[2 * SH];                   // transposed h1
// Region-1 weights (h0-driven), per-lane float2 {U0, W1}:
__device__ float g_WC[(size_t)NBLK * 1024 * 64];    // 32 MB
// Region-2 weights (h1-driven): U1
__device__ float g_WD[(size_t)NBLK * 1024 * 32];    // 16 MB

// grid barrier state: per-block arrival flags + release generation
__device__ volatile unsigned g_flags[NBLK];
__device__ volatile unsigned g_relgen;

// ---------------------------------------------------------------------------
// packed f32x2 helpers (sm_103a dual-fp32 pipe, PTX-only)
// ---------------------------------------------------------------------------
__device__ __forceinline__ ull ffma2_(ull a, ull b, ull c) {
    ull d;
    asm("fma.rn.f32x2 %0, %1, %2, %3;" : "=l"(d) : "l"(a), "l"(b), "l"(c));
    return d;
}
__device__ __forceinline__ ull addf2_(ull a, ull b) {
    ull d;
    asm("add.rn.f32x2 %0, %1, %2;" : "=l"(d) : "l"(a), "l"(b));
    return d;
}
__device__ __forceinline__ float2 unpack2_(ull v) {
    float2 r;
    asm("mov.b64 {%0, %1}, %2;" : "=f"(r.x), "=f"(r.y) : "l"(v));
    return r;
}
__device__ __forceinline__ ull dup2_(float f) {
    ull d;
    asm("mov.b64 %0, {%1, %1};" : "=l"(d) : "f"(f));
    return d;
}

// cp.async, L2-only (.cg) — bypasses L1 so cross-SM h updates are never stale
__device__ __forceinline__ void cp16_(uint32_t dst, const void* src) {
    asm volatile("cp.async.cg.shared.global [%0], [%1], 16;" :: "r"(dst), "l"(src));
}
#define CPCOMMIT() asm volatile("cp.async.commit_group;" ::: "memory")
#define CPWAIT1()  asm volatile("cp.async.wait_group 1;"  ::: "memory")

__device__ __forceinline__ float sigmoidf_(float v) {
    return 1.f / (1.f + __expf(-v));
}

// ---------------------------------------------------------------------------
__global__ void k_init() {
    int idx = blockIdx.x * blockDim.x + threadIdx.x;
    if (idx < 2 * SH) { g_h0T[idx] = 0.f; g_h1T[idx] = 0.f; }
    if (idx < NBLK) g_flags[idx] = 0;
    if (idx == 0) g_relgen = 0;
}

// ---------------------------------------------------------------------------
// k_prep: pack recurrent weights into block-major lane streams.
// ---------------------------------------------------------------------------
__global__ void k_prep(const float* __restrict__ U0, const float* __restrict__ W1,
                       const float* __restrict__ U1) {
    int idx = blockIdx.x * blockDim.x + threadIdx.x;
    const int NWC = NBLK * 1024 * 64;      // 8M
    const int NWD = NBLK * 1024 * 32;      // 4M
    if (idx < NWC) {
        int lane2 = idx & 63, k = (idx >> 6) & 1023, b = idx >> 16;
        int lane = lane2 >> 1, which = lane2 & 1;
        int col = (lane >> 3) * NH + b * 8 + (lane & 7);
        g_WC[idx] = which ? W1[(size_t)k * NZ + col] : U0[(size_t)k * NZ + col];
    }
    if (idx < NWD) {
        int lane = idx & 31, k = (idx >> 5) & 1023, b = idx >> 15;
        int col = (lane >> 3) * NH + b * 8 + (lane & 7);
        g_WD[idx] = U1[(size_t)k * NZ + col];
    }
}

// ---------------------------------------------------------------------------
// k_xin: xin[r, n] = tanh( x[b,t,:] @ Wi[:,n] + bi[n] ),  r = t*NB + b
// ---------------------------------------------------------------------------
__global__ __launch_bounds__(256) void k_xin(const float* __restrict__ x,
                                             const float* __restrict__ Wi,
                                             const float* __restrict__ bi) {
    __shared__ float As[16][64];
    __shared__ float Bs[16][64];
    int tid = threadIdx.x;
    int tx = tid & 15, ty = tid >> 4;
    int n0 = blockIdx.x * 64;
    int row0 = blockIdx.y * 64;

    float acc[4][4] = {};

    int ar = tid & 63, akq = tid >> 6;
    int R = row0 + ar;
    int bb = R & 63, tt = R >> 6;               // r = t*NB + b
    const float* aptr = x + ((size_t)bb * NT + tt) * NF + akq * 4;
    int bkk = tid >> 4, bnq = tid & 15;
    const float* bptr = Wi + (size_t)bkk * NDIN + n0 + bnq * 4;

    float4 pa = *(const float4*)aptr;
    float4 pb = *(const float4*)bptr;

    const int NC = NF / 16;
    for (int c = 0; c < NC; c++) {
        As[akq * 4 + 0][ar] = pa.x; As[akq * 4 + 1][ar] = pa.y;
        As[akq * 4 + 2][ar] = pa.z; As[akq * 4 + 3][ar] = pa.w;
        *(float4*)&Bs[bkk][bnq * 4] = pb;
        __syncthreads();
        if (c + 1 < NC) {
            pa = *(const float4*)(aptr + (c + 1) * 16);
            pb = *(const float4*)(bptr + (size_t)(c + 1) * 16 * NDIN);
        }
#pragma unroll
        for (int kk = 0; kk < 16; kk++) {
            float4 a = *(const float4*)&As[kk][ty * 4];
            float4 b = *(const float4*)&Bs[kk][tx * 4];
            acc[0][0] += a.x * b.x; acc[0][1] += a.x * b.y; acc[0][2] += a.x * b.z; acc[0][3] += a.x * b.w;
            acc[1][0] += a.y * b.x; acc[1][1] += a.y * b.y; acc[1][2] += a.y * b.z; acc[1][3] += a.y * b.w;
            acc[2][0] += a.z * b.x; acc[2][1] += a.z * b.y; acc[2][2] += a.z * b.z; acc[2][3] += a.z * b.w;
            acc[3][0] += a.w * b.x; acc[3][1] += a.w * b.y; acc[3][2] += a.w * b.z; acc[3][3] += a.w * b.w;
        }
        __syncthreads();
    }
#pragma unroll
    for (int i = 0; i < 4; i++) {
        int r = row0 + ty * 4 + i;
#pragma unroll
        for (int jx = 0; jx < 4; jx++) {
            int n = n0 + tx * 4 + jx;
            g_xin[(size_t)r * NDIN + n] = tanhf(acc[i][jx] + bi[n]);
        }
    }
}

// ---------------------------------------------------------------------------
// k_p0 v4: P0 = xin @ W0 + b0. FFMA2 inner + ping-pong double-buffered smem
// (one __syncthreads per chunk).
// ---------------------------------------------------------------------------
__global__ __launch_bounds__(256) void k_p0(const float* __restrict__ W0,
                                            const float* __restrict__ b0) {
    __shared__ float As[2][16][128];
    __shared__ float Bs[2][16][64];
    int tid = threadIdx.x;
    int tx = tid & 15, ty = tid >> 4;
    int n0 = blockIdx.x * 64;
    int row0 = blockIdx.y * 128;

    ull acc[8][2] = {};              // [row][colpair]

    int ar = tid & 127, akq0 = tid >> 7;
    const float* aptr0 = g_xin + (size_t)(row0 + ar) * NDIN + akq0 * 4;
    const float* aptr1 = g_xin + (size_t)(row0 + ar) * NDIN + (akq0 + 2) * 4;
    int bkk = tid >> 4, bnq = tid & 15;
    const float* bptr = W0 + (size_t)bkk * NZ + n0 + bnq * 4;

    float4 pa0 = *(const float4*)aptr0;
    float4 pa1 = *(const float4*)aptr1;
    float4 pb  = *(const float4*)bptr;

    // stage chunk 0
    As[0][akq0 * 4 + 0][ar] = pa0.x; As[0][akq0 * 4 + 1][ar] = pa0.y;
    As[0][akq0 * 4 + 2][ar] = pa0.z; As[0][akq0 * 4 + 3][ar] = pa0.w;
    As[0][(akq0 + 2) * 4 + 0][ar] = pa1.x; As[0][(akq0 + 2) * 4 + 1][ar] = pa1.y;
    As[0][(akq0 + 2) * 4 + 2][ar] = pa1.z; As[0][(akq0 + 2) * 4 + 3][ar] = pa1.w;
    *(float4*)&Bs[0][bkk][bnq * 4] = pb;
    __syncthreads();

    const int NC = NDIN / 16;
    for (int c = 0; c < NC; c++) {
        int cur = c & 1;
        if (c + 1 < NC) {
            pa0 = *(const float4*)(aptr0 + (c + 1) * 16);
            pa1 = *(const float4*)(aptr1 + (c + 1) * 16);
            pb  = *(const float4*)(bptr + (size_t)(c + 1) * 16 * NZ);
        }
#pragma unroll
        for (int kk = 0; kk < 16; kk++) {
            float4 a0 = *(const float4*)&As[cur][kk][ty * 8];
            float4 a1 = *(const float4*)&As[cur][kk][ty * 8 + 4];
            ulonglong2 b = *(const ulonglong2*)&Bs[cur][kk][tx * 4];
            ull d;
            d = dup2_(a0.x); acc[0][0] = ffma2_(d, b.x, acc[0][0]); acc[0][1] = ffma2_(d, b.y, acc[0][1]);
            d = dup2_(a0.y); acc[1][0] = ffma2_(d, b.x, acc[1][0]); acc[1][1] = ffma2_(d, b.y, acc[1][1]);
            d = dup2_(a0.z); acc[2][0] = ffma2_(d, b.x, acc[2][0]); acc[2][1] = ffma2_(d, b.y, acc[2][1]);
            d = dup2_(a0.w); acc[3][0] = ffma2_(d, b.x, acc[3][0]); acc[3][1] = ffma2_(d, b.y, acc[3][1]);
            d = dup2_(a1.x); acc[4][0] = ffma2_(d, b.x, acc[4][0]); acc[4][1] = ffma2_(d, b.y, acc[4][1]);
            d = dup2_(a1.y); acc[5][0] = ffma2_(d, b.x, acc[5][0]); acc[5][1] = ffma2_(d, b.y, acc[5][1]);
            d = dup2_(a1.z); acc[6][0] = ffma2_(d, b.x, acc[6][0]); acc[6][1] = ffma2_(d, b.y, acc[6][1]);
            d = dup2_(a1.w); acc[7][0] = ffma2_(d, b.x, acc[7][0]); acc[7][1] = ffma2_(d, b.y, acc[7][1]);
        }
        if (c + 1 < NC) {
            int nxt = cur ^ 1;
            As[nxt][akq0 * 4 + 0][ar] = pa0.x; As[nxt][akq0 * 4 + 1][ar] = pa0.y;
            As[nxt][akq0 * 4 + 2][ar] = pa0.z; As[nxt][akq0 * 4 + 3][ar] = pa0.w;
            As[nxt][(akq0 + 2) * 4 + 0][ar] = pa1.x; As[nxt][(akq0 + 2) * 4 + 1][ar] = pa1.y;
            As[nxt][(akq0 + 2) * 4 + 2][ar] = pa1.z; As[nxt][(akq0 + 2) * 4 + 3][ar] = pa1.w;
            *(float4*)&Bs[nxt][bkk][bnq * 4] = pb;
        }
        __syncthreads();
    }
#pragma unroll
    for (int i = 0; i < 8; i++) {
        int r = row0 + ty * 8 + i;
        int n = n0 + tx * 4;
        float2 vA = unpack2_(acc[i][0]);
        float2 vB = unpack2_(acc[i][1]);
        g_P0[(size_t)r * NZ + n + 0] = vA.x + b0[n + 0];
        g_P0[(size_t)r * NZ + n + 1] = vA.y + b0[n + 1];
        g_P0[(size_t)r * NZ + n + 2] = vB.x + b0[n + 2];
        g_P0[(size_t)r * NZ + n + 3] = vB.y + b0[n + 3];
    }
}

// ---------------------------------------------------------------------------
// flag-array grid barrier: per-block arrival (distinct addresses), block 0
// aggregates, single release word. ph must increase monotonically.
// ---------------------------------------------------------------------------
__device__ __forceinline__ void grid_sync_(int bid, unsigned ph) {
    __syncthreads();
    if (threadIdx.x == 0) {
        __threadfence();
        g_flags[bid] = ph;
    }
    if (bid == 0) {
        if (threadIdx.x < NBLK) {
            while (g_flags[threadIdx.x] < ph) { }
        }
        __syncthreads();
        if (threadIdx.x == 0) g_relgen = ph;
    }
    if (threadIdx.x == 0) {
        while (g_relgen < ph) { }
        __threadfence();
    }
    __syncthreads();
}

// ---------------------------------------------------------------------------
// 4x4 transpose among lanes {u, u+8, u+16, u+24} (bits 3,4 of lane).
// ---------------------------------------------------------------------------
__device__ __forceinline__ void transpose4_(ull acc[4], int g) {
    ull x0 = (g & 1) ? acc[0] : acc[1];
    ull x1 = (g & 1) ? acc[2] : acc[3];
    x0 = __shfl_xor_sync(0xffffffffu, x0, 8);
    x1 = __shfl_xor_sync(0xffffffffu, x1, 8);
    if (g & 1) { acc[0] = x0; acc[2] = x1; } else { acc[1] = x0; acc[3] = x1; }
    x0 = (g & 2) ? acc[0] : acc[2];
    x1 = (g & 2) ? acc[1] : acc[3];
    x0 = __shfl_xor_sync(0xffffffffu, x0, 16);
    x1 = __shfl_xor_sync(0xffffffffu, x1, 16);
    if (g & 2) { acc[0] = x0; acc[1] = x1; } else { acc[2] = x0; acc[3] = x1; }
}

// ---------------------------------------------------------------------------
// k_rnn v5: merged-phase recurrence + dual epilogue.
// Phase p: z0(p) (h0(p+1), p<512) and z1(p-1) (h1(p), p>0) in one 3072-K
// pass, one grid sync. 4-way split-K, named barrier per grp.
// Tail: grp 0 reduces+finishes layer 0 (c0 regs), grp 1 layer 1 (c1 regs),
// concurrently. zredA: partials from grps 1-3; zredB: from grps 0,2,3.
// ---------------------------------------------------------------------------
__global__ __launch_bounds__(RNN_THREADS, 1) void k_rnn(const float* __restrict__ b1) {
    extern __shared__ __align__(16) unsigned char sraw[];
    // hs [4][2][32][64] 64KB | ws [4][2][2048f] 64KB | zredA 24KB | zredB 24KB
    ull* zredA = (ull*)(sraw + 131072);
    ull* zredB = zredA + 3072;

    int tid = threadIdx.x;
    int grp = tid >> 7, gtid = tid & 127;
    int wg = (gtid >> 5), lane = tid & 31;
    int u = lane & 7, g = lane >> 3;
    int bid = blockIdx.x, j = bid * 8 + u;
    int R = wg * 16 + g * 4;                     // epilogue base row

    uint32_t sbase = (uint32_t)__cvta_generic_to_shared(sraw);
    uint32_t hdst = sbase + grp * 16384;
    uint32_t wdst = sbase + 65536 + grp * 16384;
    const float* hs_rd = (const float*)sraw + grp * 4096;
    const float* ws_rd = (const float*)(sraw + 65536) + grp * 4096;

    const float* wcg = g_WC + (size_t)bid * 1024 * 64 + (size_t)grp * 256 * 64;
    const float* wdg = g_WD + (size_t)bid * 1024 * 32 + (size_t)grp * 256 * 32;

    float b1v[4];
#pragma unroll
    for (int m = 0; m < 4; m++) b1v[m] = b1[m * NH + j];
    float c0[4] = {0.f, 0.f, 0.f, 0.f};
    float c1[4] = {0.f, 0.f, 0.f, 0.f};

    for (int p = 0; p <= NT; p++) {
        int par = p & 1;
        const float* h0g = g_h0T + (size_t)par * SH + (size_t)grp * 256 * 64;
        const float* h1g = g_h1T + (size_t)(par ^ 1) * SH + (size_t)grp * 256 * 64;
        float* h0w = g_h0T + (size_t)(par ^ 1) * SH;   // h0(p+1)
        float* h1w = g_h1T + (size_t)par * SH;         // h1(p)

        // P0 prefetch for layer-0 epilogue (grp 0 only, p<512)
        float pz[4][4];
        if (grp == 0 && p < NT) {
            size_t pb = ((size_t)p * NB + R) * NZ + j;
#pragma unroll
            for (int r = 0; r < 4; r++)
#pragma unroll
                for (int m = 0; m < 4; m++)
                    pz[r][m] = g_P0[pb + (size_t)r * NZ + m * NH];
        }

        ull accA[8] = {0ull,0ull,0ull,0ull,0ull,0ull,0ull,0ull};
        ull accB[8] = {0ull,0ull,0ull,0ull,0ull,0ull,0ull,0ull};

        auto barg = [&] {
            asm volatile("bar.sync %0, %1;" :: "r"(grp + 1), "r"(128) : "memory");
        };
        auto load = [&](int buf, int c) {
            const char* hp;
            const char* wp;
            int nw;
            if (c < 8) {
                hp = (const char*)(h0g + c * 2048);
                wp = (const char*)(wcg + (size_t)c * 2048);
                nw = 4;
            } else {
                hp = (const char*)(h1g + (c - 8) * 2048);
                wp = (const char*)(wdg + (size_t)(c - 8) * 1024);
                nw = 2;
            }
            hp += gtid * 16;
            uint32_t hd = hdst + buf * 8192 + gtid * 16;
            cp16_(hd, hp); cp16_(hd + 2048, hp + 2048);
            cp16_(hd + 4096, hp + 4096); cp16_(hd + 6144, hp + 6144);
            wp += gtid * 16;
            uint32_t wd = wdst + buf * 8192 + gtid * 16;
            cp16_(wd, wp); cp16_(wd + 2048, wp + 2048);
            if (nw == 4) { cp16_(wd + 4096, wp + 4096); cp16_(wd + 6144, wp + 6144); }
        };

        load(0, 0); CPCOMMIT();
        load(1, 1); CPCOMMIT();
        CPWAIT1(); barg();

        for (int c = 0; c < 16; c++) {
            int buf = c & 1;
            const float* hC = hs_rd + buf * 2048 + wg * 16;
            if (c < 8) {
                const float2* wC = (const float2*)(ws_rd + buf * 2048);
#pragma unroll 8
                for (int kk = 0; kk < KCH; kk++) {
                    ulonglong2 hA = *(const ulonglong2*)(hC + kk * 64);
                    ulonglong2 hB = *(const ulonglong2*)(hC + kk * 64 + 4);
                    ulonglong2 hCc = *(const ulonglong2*)(hC + kk * 64 + 8);
                    ulonglong2 hD = *(const ulonglong2*)(hC + kk * 64 + 12);
                    float2 wv = wC[kk * 32 + lane];
                    ull d0 = dup2_(wv.x);
                    ull d1 = dup2_(wv.y);
                    accA[0] = ffma2_(hA.x, d0, accA[0]);
                    accA[1] = ffma2_(hA.y, d0, accA[1]);
                    accA[2] = ffma2_(hB.x, d0, accA[2]);
                    accA[3] = ffma2_(hB.y, d0, accA[3]);
                    accA[4] = ffma2_(hCc.x, d0, accA[4]);
                    accA[5] = ffma2_(hCc.y, d0, accA[5]);
                    accA[6] = ffma2_(hD.x, d0, accA[6]);
                    accA[7] = ffma2_(hD.y, d0, accA[7]);
                    accB[0] = ffma2_(hA.x, d1, accB[0]);
                    accB[1] = ffma2_(hA.y, d1, accB[1]);
                    accB[2] = ffma2_(hB.x, d1, accB[2]);
                    accB[3] = ffma2_(hB.y, d1, accB[3]);
                    accB[4] = ffma2_(hCc.x, d1, accB[4]);
                    accB[5] = ffma2_(hCc.y, d1, accB[5]);
                    accB[6] = ffma2_(hD.x, d1, accB[6]);
                    accB[7] = ffma2_(hD.y, d1, accB[7]);
                }
            } else {
                const float* wC = ws_rd + buf * 2048;
#pragma unroll 8
                for (int kk = 0; kk < KCH; kk++) {
                    ulonglong2 hA = *(const ulonglong2*)(hC + kk * 64);
                    ulonglong2 hB = *(const ulonglong2*)(hC + kk * 64 + 4);
                    ulonglong2 hCc = *(const ulonglong2*)(hC + kk * 64 + 8);
                    ulonglong2 hD = *(const ulonglong2*)(hC + kk * 64 + 12);
                    ull d1 = dup2_(wC[kk * 32 + lane]);
                    accB[0] = ffma2_(hA.x, d1, accB[0]);
                    accB[1] = ffma2_(hA.y, d1, accB[1]);
                    accB[2] = ffma2_(hB.x, d1, accB[2]);
                    accB[3] = ffma2_(hB.y, d1, accB[3]);
                    accB[4] = ffma2_(hCc.x, d1, accB[4]);
                    accB[5] = ffma2_(hCc.y, d1, accB[5]);
                    accB[6] = ffma2_(hD.x, d1, accB[6]);
                    accB[7] = ffma2_(hD.y, d1, accB[7]);
                }
            }
            barg();
            if (c + 2 < 16) load(buf, c + 2);
            CPCOMMIT(); CPWAIT1(); barg();
        }

        // ---- write partials (A: grps 1-3; B: grps 0,2,3) ----
        if (grp != 0) {
            int base = ((grp - 1) * 4 + wg) * 8;
#pragma unroll
            for (int s = 0; s < 8; s++) zredA[(base + s) * 32 + lane] = accA[s];
        }
        if (grp != 1) {
            int qb = (grp == 0) ? 0 : grp - 1;
            int base = (qb * 4 + wg) * 8;
#pragma unroll
            for (int s = 0; s < 8; s++) zredB[(base + s) * 32 + lane] = accB[s];
        }
        __syncthreads();

        if (grp == 0 && p < NT) {
            // ---- layer-0 epilogue: h0(p+1) ----
#pragma unroll
            for (int q = 0; q < 3; q++) {
                int base = (q * 4 + wg) * 8;
#pragma unroll
                for (int s = 0; s < 8; s++)
                    accA[s] = addf2_(accA[s], zredA[(base + s) * 32 + lane]);
            }
            ull aE[4] = {accA[0], accA[2], accA[4], accA[6]};
            ull aO[4] = {accA[1], accA[3], accA[5], accA[7]};
            transpose4_(aE, g);
            transpose4_(aO, g);
            float zg[4][4];
#pragma unroll
            for (int m = 0; m < 4; m++) {
                float2 e = unpack2_(aE[m]), o = unpack2_(aO[m]);
                zg[m][0] = e.x; zg[m][1] = e.y; zg[m][2] = o.x; zg[m][3] = o.y;
            }
            float hv[4];
#pragma unroll
            for (int r = 0; r < 4; r++) {
                float ig = sigmoidf_(zg[0][r] + pz[r][0]);
                float fg = sigmoidf_(zg[1][r] + pz[r][1]);
                float gg = tanhf(zg[2][r] + pz[r][2]);
                float og = sigmoidf_(zg[3][r] + pz[r][3]);
                c0[r] = fg * c0[r] + ig * gg;
                hv[r] = og * tanhf(c0[r]);
            }
            *(float4*)&h0w[j * 64 + R] = make_float4(hv[0], hv[1], hv[2], hv[3]);
        } else if (grp == 1 && p > 0) {
            // ---- layer-1 epilogue: h1(p) ----
#pragma unroll
            for (int q = 0; q < 3; q++) {
                int base = (q * 4 + wg) * 8;
#pragma unroll
                for (int s = 0; s < 8; s++)
                    accB[s] = addf2_(accB[s], zredB[(base + s) * 32 + lane]);
            }
            ull aE[4] = {accB[0], accB[2], accB[4], accB[6]};
            ull aO[4] = {accB[1], accB[3], accB[5], accB[7]};
            transpose4_(aE, g);
            transpose4_(aO, g);
            float zg[4][4];
#pragma unroll
            for (int m = 0; m < 4; m++) {
                float2 e = unpack2_(aE[m]), o = unpack2_(aO[m]);
                zg[m][0] = e.x; zg[m][1] = e.y; zg[m][2] = o.x; zg[m][3] = o.y;
            }
            float hv[4];
#pragma unroll
            for (int r = 0; r < 4; r++) {
                float ig = sigmoidf_(zg[0][r] + b1v[0]);
                float fg = sigmoidf_(zg[1][r] + b1v[1]);
                float gg = tanhf(zg[2][r] + b1v[2]);
                float og = sigmoidf_(zg[3][r] + b1v[3]);
                c1[r] = fg * c1[r] + ig * gg;
                hv[r] = og * tanhf(c1[r]);
            }
            *(float4*)&h1w[j * 64 + R] = make_float4(hv[0], hv[1], hv[2], hv[3]);
        }
        grid_sync_(bid, (unsigned)(p + 1));
    }
}

// ---------------------------------------------------------------------------
// k_out: out = tanh( h1_final @ Wo + bo ),  h1 stored transposed hT[k][b]
// ---------------------------------------------------------------------------
__global__ void k_out(const float* __restrict__ Wo, const float* __restrict__ bo,
                      float* __restrict__ out) {
    int idx = blockIdx.x * blockDim.x + threadIdx.x;
    if (idx >= NB * NDOUT) return;
    int n = idx & 127, b = idx >> 7;
    const float* hT = g_h1T;   // h1(512) at parity 0
    float s0 = 0.f, s1 = 0.f, s2 = 0.f, s3 = 0.f;
#pragma unroll 4
    for (int k = 0; k < NH; k += 4) {
        s0 += hT[(k + 0) * 64 + b] * Wo[(size_t)(k + 0) * NDOUT + n];
        s1 += hT[(k + 1) * 64 + b] * Wo[(size_t)(k + 1) * NDOUT + n];
        s2 += hT[(k + 2) * 64 + b] * Wo[(size_t)(k + 2) * NDOUT + n];
        s3 += hT[(k + 3) * 64 + b] * Wo[(size_t)(k + 3) * NDOUT + n];
    }
    out[idx] = tanhf((s0 + s1) + (s2 + s3) + bo[n]);
}

// ---------------------------------------------------------------------------
extern "C" void kernel_launch(void* const* d_in, const int* in_sizes, int n_in,
                              void* d_out, int out_size) {
    const float* x  = (const float*)d_in[0];
    const float* Wi = (const float*)d_in[1];
    const float* bi = (const float*)d_in[2];
    const float* W0 = (const float*)d_in[3];
    const float* U0 = (const float*)d_in[4];
    const float* b0 = (const float*)d_in[5];
    const float* W1 = (const float*)d_in[6];
    const float* U1 = (const float*)d_in[7];
    const float* b1 = (const float*)d_in[8];
    const float* Wo = (const float*)d_in[9];
    const float* bo = (const float*)d_in[10];
    float* out = (float*)d_out;
    (void)in_sizes; (void)n_in; (void)out_size;

    cudaFuncSetAttribute(k_rnn, cudaFuncAttributeMaxDynamicSharedMemorySize, RNN_SMEM);

    k_init<<<512, 256>>>();
    k_prep<<<32768, 256>>>(U0, W1, U1);
    k_xin<<<dim3(16, 512), 256>>>(x, Wi, bi);
    k_p0<<<dim3(64, 256), 256>>>(W0, b0);
    k_rnn<<<NBLK, RNN_THREADS, RNN_SMEM>>>(b1);
    k_out<<<32, 256>>>(Wo, bo, out);
}